// round 13
// baseline (speedup 1.0000x reference)
#include <cuda_runtime.h>
#include <cuda_bf16.h>
#include <math.h>
#include <stdint.h>

// ----------------------- problem dims -----------------------
// B=64, S_SRC=128, T_TRG=64 -> TDEC=63, E=512, H=1024, 4H=4096, NL=2
// SOS=1, SCALE=sqrt(512)

typedef unsigned long long u64;

#define FMA2(acc, a, b) asm("fma.rn.f32x2 %0, %1, %2, %3;" : "=l"(acc) : "l"(a), "l"(b), "l"(acc))

__device__ __forceinline__ float psum(u64 v) {
    float lo, hi;
    asm("mov.b64 {%0,%1}, %2;" : "=f"(lo), "=f"(hi) : "l"(v));
    return lo + hi;
}

__device__ __forceinline__ void cp16(unsigned dst, const void* src) {
    asm volatile("cp.async.cg.shared.global [%0], [%1], 16;" :: "r"(dst), "l"(src));
}
#define CP_COMMIT() asm volatile("cp.async.commit_group;")

__device__ __forceinline__ void ldsm4(unsigned* r, uint32_t addr) {
    asm volatile("ldmatrix.sync.aligned.m8n8.x4.shared.b16 {%0,%1,%2,%3}, [%4];"
                 : "=r"(r[0]), "=r"(r[1]), "=r"(r[2]), "=r"(r[3]) : "r"(addr));
}

__device__ __forceinline__ void mma16816(float* d, const unsigned* a, const unsigned* b) {
    asm volatile(
        "mma.sync.aligned.m16n8k16.row.col.f32.bf16.bf16.f32 "
        "{%0,%1,%2,%3}, {%4,%5,%6,%7}, {%8,%9}, {%0,%1,%2,%3};"
        : "+f"(d[0]), "+f"(d[1]), "+f"(d[2]), "+f"(d[3])
        : "r"(a[0]), "r"(a[1]), "r"(a[2]), "r"(a[3]), "r"(b[0]), "r"(b[1]));
}

__device__ __forceinline__ float sigm(float x) {
    float e = __expf(-x);
    return __fdividef(1.f, 1.f + e);
}
__device__ __forceinline__ float tanh_f(float x) {
    float xx = fminf(fmaxf(x, -30.f), 30.f);
    float e = __expf(-2.f * xx);
    return __fdividef(1.f - e, 1.f + e);
}

// ----------------------- device scratch (no allocation) -----------------------
__device__ float g_srcemb[8192 * 512];
__device__ float g_pre[8192 * 4096];
__device__ float g_preds[4032 * 512];
__device__ float g_scores[4032 * 128];
__device__ float g_cstate[2 * 64 * 1024];
__device__ __nv_bfloat16 g_wpk[4][128 * 64 * 1024];
__device__ __nv_bfloat16 g_wihpk[4][2 * 4096 * 1024];
__device__ __nv_bfloat16 g_fcpk[2 * 512 * 1024];
__device__ __nv_bfloat16 g_srcpk[2 * 8192 * 512];
__device__ __nv_bfloat16 g_decpk[2 * 4032 * 512];
__device__ __nv_bfloat16 g_seqApk[2 * 8192 * 1024];
__device__ __nv_bfloat16 g_dseqApk[2 * 4032 * 1024];
__device__ __nv_bfloat16 g_dseqBpk[2 * 4032 * 1024];
__device__ __nv_bfloat16 g_hpk[2][2][128 * 1024];
// per-chunk h-ready flags: [layer][chunk][pad to 32B]
__device__ unsigned g_hflag[4][16][8];

// ----------------------- init -----------------------
__global__ void zero_init() {
    int i = blockIdx.x * 256 + threadIdx.x;
    if (i < 2 * 64 * 1024) g_cstate[i] = 0.f;
    if (i < 128 * 1024 / 2) {
        ((uint32_t*)g_hpk[0][0])[i] = 0u;
        ((uint32_t*)g_hpk[1][0])[i] = 0u;
    }
    if (i < 4 * 16 * 8) ((unsigned*)g_hflag)[i] = 0u;
}

// ----------------------- Whh -> packed bf16 hi/lo -----------------------
__global__ void prep_w4(const float* __restrict__ w0, const float* __restrict__ w1,
                        const float* __restrict__ w2, const float* __restrict__ w3) {
    int l = blockIdx.y;
    const float* Whh = (l == 0) ? w0 : (l == 1) ? w1 : (l == 2) ? w2 : w3;
    __nv_bfloat16* dst0 = &g_wpk[l][0];
    int bx = blockIdx.x;
    __nv_bfloat16* dst = dst0 + ((long long)bx << 16);
    for (int i = threadIdx.x; i < 64 * 1024; i += 256) {
        int r = i >> 10, k = i & 1023;
        int part = r >> 5, rr = r & 31;
        int grow = (rr >> 3) * 1024 + bx * 8 + (rr & 7);
        float v = Whh[(long long)grow * 1024 + k];
        __nv_bfloat16 hi = __float2bfloat16(v);
        if (part == 0) dst[i] = hi;
        else dst[i] = __float2bfloat16(v - __bfloat162float(hi));
    }
}

// ----------------------- all Wih + fcW -> bf16 hi/lo planes (one launch) -----------------------
__global__ void prep_all(const float* __restrict__ w0, const float* __restrict__ w1,
                         const float* __restrict__ w2, const float* __restrict__ w3,
                         const float* __restrict__ w4) {
    int j = blockIdx.y;
    const float* W;
    __nv_bfloat16* d;
    long long n;
    if (j == 0)      { W = w0; d = &g_wihpk[0][0]; n = 4096LL * 512; }
    else if (j == 1) { W = w1; d = &g_wihpk[1][0]; n = 4096LL * 1024; }
    else if (j == 2) { W = w2; d = &g_wihpk[2][0]; n = 4096LL * 512; }
    else if (j == 3) { W = w3; d = &g_wihpk[3][0]; n = 4096LL * 1024; }
    else             { W = w4; d = &g_fcpk[0];     n = 512LL * 1024; }
    for (long long i = blockIdx.x * 256 + threadIdx.x; i < n; i += (long long)gridDim.x * 256) {
        float v = W[i];
        __nv_bfloat16 hi = __float2bfloat16(v);
        d[i] = hi;
        d[n + i] = __float2bfloat16(v - __bfloat162float(hi));
    }
}

// ----------------------- embedding gathers -----------------------
__global__ void gather_src(const int* __restrict__ src, const float* __restrict__ tab,
                           float* __restrict__ out, __nv_bfloat16* __restrict__ pk) {
    int row = blockIdx.x;
    int tok = src[row];
    const float4* r = (const float4*)(tab + (long long)tok * 512);
    float4 v = r[threadIdx.x];
    ((float4*)(out + (long long)row * 512))[threadIdx.x] = v;
    const long long PL = 8192LL * 512;
    __nv_bfloat16 hx = __float2bfloat16(v.x), hy = __float2bfloat16(v.y);
    __nv_bfloat16 hz = __float2bfloat16(v.z), hw = __float2bfloat16(v.w);
    long long o = (long long)row * 512 + threadIdx.x * 4;
    pk[o] = hx; pk[o + 1] = hy; pk[o + 2] = hz; pk[o + 3] = hw;
    pk[PL + o]     = __float2bfloat16(v.x - __bfloat162float(hx));
    pk[PL + o + 1] = __float2bfloat16(v.y - __bfloat162float(hy));
    pk[PL + o + 2] = __float2bfloat16(v.z - __bfloat162float(hz));
    pk[PL + o + 3] = __float2bfloat16(v.w - __bfloat162float(hw));
}

__global__ void gather_dec(const int* __restrict__ trg, const float* __restrict__ tab,
                           __nv_bfloat16* __restrict__ pk) {
    int row = blockIdx.x;
    int b = row / 63, t = row % 63;
    int tok = (t == 0) ? 1 : trg[b * 64 + t];
    const float4* r = (const float4*)(tab + (long long)tok * 512);
    float4 v = r[threadIdx.x];
    const long long PL = 4032LL * 512;
    __nv_bfloat16 hx = __float2bfloat16(v.x), hy = __float2bfloat16(v.y);
    __nv_bfloat16 hz = __float2bfloat16(v.z), hw = __float2bfloat16(v.w);
    long long o = (long long)row * 512 + threadIdx.x * 4;
    pk[o] = hx; pk[o + 1] = hy; pk[o + 2] = hz; pk[o + 3] = hw;
    pk[PL + o]     = __float2bfloat16(v.x - __bfloat162float(hx));
    pk[PL + o + 1] = __float2bfloat16(v.y - __bfloat162float(hy));
    pk[PL + o + 2] = __float2bfloat16(v.z - __bfloat162float(hz));
    pk[PL + o + 3] = __float2bfloat16(v.w - __bfloat162float(hw));
}

// ----------------------- bf16 HMMA GEMM: C = A@W^T + b1 + b2 -----------------------
#define GB_STG 49152
__global__ void __launch_bounds__(256, 2) gemm_bf16(
    const __nv_bfloat16* __restrict__ apk,
    const __nv_bfloat16* __restrict__ wpk,
    const float* __restrict__ b1, const float* __restrict__ b2,
    float* __restrict__ C, int M, int N, int K)
{
    extern __shared__ __align__(128) char smem[];
    uint32_t sbase = (uint32_t)__cvta_generic_to_shared(smem);
    int tid = threadIdx.x, lane = tid & 31, w = tid >> 5;
    int mg = w & 3, ng = w >> 2;
    int m0 = blockIdx.y * 128, n0 = blockIdx.x * 64;
    long long Kb = (long long)K * 2;
    const char* ah = (const char*)apk;
    const char* al = ah + (long long)M * K * 2;
    const char* bh = (const char*)wpk;
    const char* bl = bh + (long long)N * K * 2;
    int nch = K >> 6;

    int arow = tid >> 3, acol = tid & 7;
#pragma unroll
    for (int s = 0; s < 2; s++) {
        uint32_t base = sbase + s * GB_STG;
#pragma unroll
        for (int i = 0; i < 4; i++) {
            int row = arow + i * 32;
            int gr = m0 + row; if (gr >= M) gr = M - 1;
            uint32_t d = row * 128 + ((acol ^ (row & 7)) << 4);
            cp16(base + d, ah + gr * Kb + s * 128 + acol * 16);
            cp16(base + 16384 + d, al + gr * Kb + s * 128 + acol * 16);
        }
#pragma unroll
        for (int i = 0; i < 2; i++) {
            int row = arow + i * 32;
            if (row < 64) {
                uint32_t d = row * 128 + ((acol ^ (row & 7)) << 4);
                cp16(base + 32768 + d, bh + (long long)(n0 + row) * Kb + s * 128 + acol * 16);
                cp16(base + 40960 + d, bl + (long long)(n0 + row) * Kb + s * 128 + acol * 16);
            }
        }
        CP_COMMIT();
    }

    int matA = lane >> 3;
    int rAoff = (matA & 1) * 8 + (lane & 7);
    int kselA = matA >> 1;
    int rBoff = ((lane >> 4) & 1) * 8 + (lane & 7);
    int kselB = (lane >> 3) & 1;

    float acc[2][4][4];
#pragma unroll
    for (int a = 0; a < 2; a++)
#pragma unroll
        for (int j = 0; j < 4; j++)
#pragma unroll
            for (int k = 0; k < 4; k++) acc[a][j][k] = 0.f;

    for (int c = 0; c < nch; c++) {
        asm volatile("cp.async.wait_group 1;" ::: "memory");
        __syncthreads();

        uint32_t aH = sbase + (c & 1) * GB_STG;
        uint32_t aL = aH + 16384, bH = aH + 32768, bL = aH + 40960;
#pragma unroll
        for (int kt = 0; kt < 4; kt++) {
            unsigned afh[2][4], afl[2][4];
#pragma unroll
            for (int mt = 0; mt < 2; mt++) {
                int row = 32 * mg + 16 * mt + rAoff;
                int col = kt * 2 + kselA;
                uint32_t sw = row * 128 + ((col ^ (row & 7)) << 4);
                ldsm4(afh[mt], aH + sw);
                ldsm4(afl[mt], aL + sw);
            }
#pragma unroll
            for (int bt = 0; bt < 2; bt++) {
                int row = 32 * ng + 16 * bt + rBoff;
                int col = kt * 2 + kselB;
                uint32_t sw = row * 128 + ((col ^ (row & 7)) << 4);
                unsigned bfh[4], bfl[4];
                ldsm4(bfh, bH + sw);
                ldsm4(bfl, bL + sw);
#pragma unroll
                for (int mt = 0; mt < 2; mt++) {
                    mma16816(acc[mt][2 * bt + 0], afh[mt], bfh + 0);
                    mma16816(acc[mt][2 * bt + 1], afh[mt], bfh + 2);
                    mma16816(acc[mt][2 * bt + 0], afh[mt], bfl + 0);
                    mma16816(acc[mt][2 * bt + 1], afh[mt], bfl + 2);
                    mma16816(acc[mt][2 * bt + 0], afl[mt], bfh + 0);
                    mma16816(acc[mt][2 * bt + 1], afl[mt], bfh + 2);
                }
            }
        }
        __syncthreads();

        int p2 = c + 2;
        if (p2 < nch) {
            uint32_t base = sbase + (c & 1) * GB_STG;
#pragma unroll
            for (int i = 0; i < 4; i++) {
                int row = arow + i * 32;
                int gr = m0 + row; if (gr >= M) gr = M - 1;
                uint32_t d = row * 128 + ((acol ^ (row & 7)) << 4);
                cp16(base + d, ah + gr * Kb + p2 * 128 + acol * 16);
                cp16(base + 16384 + d, al + gr * Kb + p2 * 128 + acol * 16);
            }
#pragma unroll
            for (int i = 0; i < 2; i++) {
                int row = arow + i * 32;
                if (row < 64) {
                    uint32_t d = row * 128 + ((acol ^ (row & 7)) << 4);
                    cp16(base + 32768 + d, bh + (long long)(n0 + row) * Kb + p2 * 128 + acol * 16);
                    cp16(base + 40960 + d, bl + (long long)(n0 + row) * Kb + p2 * 128 + acol * 16);
                }
            }
        }
        CP_COMMIT();
    }

#pragma unroll
    for (int mt = 0; mt < 2; mt++) {
        int r0 = 32 * mg + 16 * mt + (lane >> 2);
#pragma unroll
        for (int j = 0; j < 4; j++) {
            int col = n0 + 32 * ng + 8 * j + (lane & 3) * 2;
            float bb0 = b1[col], bb1 = b1[col + 1];
            if (b2) { bb0 += b2[col]; bb1 += b2[col + 1]; }
            int gm = m0 + r0;
            if (gm < M) {
                float2 v = make_float2(acc[mt][j][0] + bb0, acc[mt][j][1] + bb1);
                *(float2*)&C[(long long)gm * N + col] = v;
            }
            if (gm + 8 < M) {
                float2 v = make_float2(acc[mt][j][2] + bb0, acc[mt][j][3] + bb1);
                *(float2*)&C[(long long)(gm + 8) * N + col] = v;
            }
        }
    }
}

// ----------------------- fp32 f32x2 GEMM (attention scores) -----------------------
__global__ void __launch_bounds__(256, 1) gemm_abt(
    const float* __restrict__ A, const float* __restrict__ W,
    const float* __restrict__ b1, const float* __restrict__ b2,
    float* __restrict__ C,
    int M, int N, int K, float alpha,
    long long strideA, long long strideW, long long strideC)
{
    A += (long long)blockIdx.z * strideA;
    W += (long long)blockIdx.z * strideW;
    C += (long long)blockIdx.z * strideC;

    __shared__ __align__(16) float As[2][128][36];
    __shared__ __align__(16) float Bs[2][64][36];

    int tid = threadIdx.x;
    int m0 = blockIdx.y * 128;
    int n0 = blockIdx.x * 64;
    int ty = tid >> 4, tx = tid & 15;

    u64 acc[8][4];
#pragma unroll
    for (int i = 0; i < 8; i++)
#pragma unroll
        for (int j = 0; j < 4; j++) acc[i][j] = 0ull;

    float4 sa[4], sb[2];
    const float4 z4 = {0.f, 0.f, 0.f, 0.f};
    int nch = K >> 5;

#pragma unroll
    for (int r = 0; r < 4; r++) {
        int li = tid + r * 256;
        int m = li >> 3, kq = li & 7;
        sa[r] = (m0 + m < M) ? *(const float4*)&A[(long long)(m0 + m) * K + kq * 4] : z4;
    }
#pragma unroll
    for (int r = 0; r < 2; r++) {
        int li = tid + r * 256;
        int n = li >> 3, kq = li & 7;
        sb[r] = *(const float4*)&W[(long long)(n0 + n) * K + kq * 4];
    }
#pragma unroll
    for (int r = 0; r < 4; r++) {
        int li = tid + r * 256;
        int m = li >> 3, kq = li & 7;
        *(float4*)&As[0][m][kq * 4] = sa[r];
    }
#pragma unroll
    for (int r = 0; r < 2; r++) {
        int li = tid + r * 256;
        int n = li >> 3, kq = li & 7;
        *(float4*)&Bs[0][n][kq * 4] = sb[r];
    }
    __syncthreads();

    for (int c = 0; c < nch; c++) {
        int cur = c & 1;
        int kc = (c + 1) << 5;
        if (c + 1 < nch) {
#pragma unroll
            for (int r = 0; r < 4; r++) {
                int li = tid + r * 256;
                int m = li >> 3, kq = li & 7;
                sa[r] = (m0 + m < M) ? *(const float4*)&A[(long long)(m0 + m) * K + kc + kq * 4] : z4;
            }
#pragma unroll
            for (int r = 0; r < 2; r++) {
                int li = tid + r * 256;
                int n = li >> 3, kq = li & 7;
                sb[r] = *(const float4*)&W[(long long)(n0 + n) * K + kc + kq * 4];
            }
        }
#pragma unroll
        for (int q = 0; q < 8; q++) {
            int k = q * 4;
            ulonglong2 a[8], ww[4];
#pragma unroll
            for (int i = 0; i < 8; i++) a[i] = *(const ulonglong2*)&As[cur][ty + 16 * i][k];
#pragma unroll
            for (int j = 0; j < 4; j++) ww[j] = *(const ulonglong2*)&Bs[cur][tx + 16 * j][k];
#pragma unroll
            for (int i = 0; i < 8; i++)
#pragma unroll
                for (int j = 0; j < 4; j++) {
                    FMA2(acc[i][j], a[i].x, ww[j].x);
                    FMA2(acc[i][j], a[i].y, ww[j].y);
                }
        }
        if (c + 1 < nch) {
            int nb = cur ^ 1;
#pragma unroll
            for (int r = 0; r < 4; r++) {
                int li = tid + r * 256;
                int m = li >> 3, kq = li & 7;
                *(float4*)&As[nb][m][kq * 4] = sa[r];
            }
#pragma unroll
            for (int r = 0; r < 2; r++) {
                int li = tid + r * 256;
                int n = li >> 3, kq = li & 7;
                *(float4*)&Bs[nb][n][kq * 4] = sb[r];
            }
        }
        __syncthreads();
    }

#pragma unroll
    for (int i = 0; i < 8; i++) {
        int m = m0 + ty + 16 * i;
        if (m >= M) continue;
#pragma unroll
        for (int j = 0; j < 4; j++) {
            int n = n0 + tx + 16 * j;
            float v = psum(acc[i][j]) * alpha;
            if (b1) v += b1[n];
            if (b2) v += b2[n];
            C[(long long)m * N + n] = v;
        }
    }
}

// ----------------------- persistent HMMA LSTM layer (barrier-free, per-chunk flags) -----------------------
// SMEM: A ring 6x16KB @0 (gs0/gs1 overlay stages 0,1 at epilogue) | W 128KB @98304. Total 229376.
#define SA_OFF 0
#define SW_OFF 98304
#define LSTM_SMEM 229376

__global__ void __launch_bounds__(512, 1) lstm_layer_mma(
    const float* __restrict__ pre,
    const __nv_bfloat16* __restrict__ wpk,
    __nv_bfloat16* __restrict__ h0,
    __nv_bfloat16* __restrict__ h1,
    float* __restrict__ cstate,
    __nv_bfloat16* __restrict__ spk,
    long long splane,
    int T, int barid)
{
    extern __shared__ __align__(128) char smem[];
    uint32_t sbase = (uint32_t)__cvta_generic_to_shared(smem);

    int tid = threadIdx.x, lane = tid & 31;
    int wgid = tid >> 8;
    int w = (tid >> 5) & 7;
    int mg = (w & 1) | ((w >> 2) << 1);
    int ng = (w >> 1) & 1;
    int bx = blockIdx.x, hbase = bx * 8;

    unsigned (*flags)[8] = g_hflag[barid];
    unsigned* myflag = &g_hflag[barid][bx >> 3][0];

    const char* wsrc = (const char*)(wpk + ((long long)bx << 16));

    // load W slice once
#pragma unroll
    for (int i = 0; i < 16; i++) {
        int v = tid + i * 512;
        int ck = v >> 9;
        int rc = v & 511;
        int row = rc >> 3, col = rc & 7;
        cp16(sbase + SW_OFF + ck * 8192 + row * 128 + ((col ^ (row & 7)) << 4),
             wsrc + row * 2048 + ck * 128 + col * 16);
    }
    CP_COMMIT();
    asm volatile("cp.async.wait_group 0;" ::: "memory");
    __syncthreads();

    int matA = lane >> 3;
    int rAoff = (matA & 1) * 8 + (lane & 7);
    int kselA = matA >> 1;
    int rBoff = ((lane >> 4) & 1) * 8 + (lane & 7);
    int kselB = (lane >> 3) & 1;

    float* gs0 = (float*)(smem + SA_OFF);            // [128][32] overlays stage 0
    float* gs1 = (float*)(smem + SA_OFF + 16384);    // [128][32] overlays stage 1

    int cb = tid >> 3, chl = tid & 7;
    int chg = hbase + chl;
    float creg = cstate[cb * 1024 + chg];

    for (int t = 0; t < T; t++) {
        const char* asrc = (const char*)((t & 1) ? h1 : h0);
        __nv_bfloat16* hout = (t & 1) ? h0 : h1;
        unsigned target = 8u * (unsigned)t;

        long long prow = ((long long)cb * T + t) * 4096;
        float pr0 = pre[prow + chg];
        float pr1 = pre[prow + 1024 + chg];
        float pr2 = pre[prow + 2048 + chg];
        float pr3 = pre[prow + 3072 + chg];

        // poll chunks 0-3 ready, then prologue loads
        if (t > 0 && tid == 0) {
#pragma unroll
            for (int ck = 0; ck < 4; ck++) {
                unsigned v;
                do {
                    asm volatile("ld.acquire.gpu.u32 %0, [%1];" : "=r"(v) : "l"(&flags[ck][0]) : "memory");
                    if (v >= target) break;
                    __nanosleep(16);
                } while (true);
            }
        }
        __syncthreads();

#pragma unroll
        for (int s = 0; s < 4; s++) {
#pragma unroll
            for (int i = 0; i < 2; i++) {
                int v = tid + i * 512, row = v >> 3, col = v & 7;
                cp16(sbase + SA_OFF + s * 16384 + row * 128 + ((col ^ (row & 7)) << 4),
                     asrc + row * 2048 + s * 128 + col * 16);
            }
            if (s & 1) CP_COMMIT();
        }

        float acc[2][2][4];
#pragma unroll
        for (int a = 0; a < 2; a++)
#pragma unroll
            for (int b = 0; b < 2; b++)
#pragma unroll
                for (int k = 0; k < 4; k++) acc[a][b][k] = 0.f;

        for (int p = 0; p < 8; p++) {
            asm volatile("cp.async.wait_group 1;" ::: "memory");
            int pn = p + 2;
            if (pn < 8 && t > 0 && tid == 0) {
#pragma unroll
                for (int s2 = 0; s2 < 2; s2++) {
                    int cc = 2 * pn + s2;
                    unsigned v;
                    do {
                        asm volatile("ld.acquire.gpu.u32 %0, [%1];" : "=r"(v) : "l"(&flags[cc][0]) : "memory");
                        if (v >= target) break;
                        __nanosleep(16);
                    } while (true);
                }
            }
            __syncthreads();

            if (pn < 8) {
#pragma unroll
                for (int s2 = 0; s2 < 2; s2++) {
                    int cc = 2 * pn + s2;
                    int st = cc % 6;
#pragma unroll
                    for (int i = 0; i < 2; i++) {
                        int v = tid + i * 512, row = v >> 3, col = v & 7;
                        cp16(sbase + SA_OFF + st * 16384 + row * 128 + ((col ^ (row & 7)) << 4),
                             asrc + row * 2048 + cc * 128 + col * 16);
                    }
                }
            }
            CP_COMMIT();

            int c = 2 * p + wgid;
            uint32_t aS = sbase + SA_OFF + (c % 6) * 16384;
            uint32_t bS = sbase + SW_OFF + c * 8192;
#pragma unroll
            for (int kt = 0; kt < 4; kt++) {
                unsigned af[2][4];
#pragma unroll
                for (int mt = 0; mt < 2; mt++) {
                    int row = 32 * mg + 16 * mt + rAoff;
                    int col = kt * 2 + kselA;
                    ldsm4(af[mt], aS + row * 128 + ((col ^ (row & 7)) << 4));
                }
#pragma unroll
                for (int pp = 0; pp < 2; pp++) {
                    if (pp == 1 && mg >= 2) break;
                    unsigned bf[4];
                    int row = 32 * pp + 16 * ng + rBoff;
                    int col = kt * 2 + kselB;
                    ldsm4(bf, bS + row * 128 + ((col ^ (row & 7)) << 4));
#pragma unroll
                    for (int mt = 0; mt < 2; mt++) {
                        mma16816(acc[mt][0], af[mt], bf + 0);
                        mma16816(acc[mt][1], af[mt], bf + 2);
                    }
                }
            }
        }

        // epilogue: each warpgroup writes its own gs region (stages 0,1 idle since pair 6)
        __syncthreads();
        {
            float* gsw = wgid ? gs1 : gs0;
#pragma unroll
            for (int mt = 0; mt < 2; mt++) {
                int row = 32 * mg + 16 * mt + (lane >> 2);
#pragma unroll
                for (int nt = 0; nt < 2; nt++) {
                    int col = 16 * ng + 8 * nt + (lane & 3) * 2;
                    *(float2*)&gsw[row * 32 + col] = make_float2(acc[mt][nt][0], acc[mt][nt][1]);
                    *(float2*)&gsw[(row + 8) * 32 + col] = make_float2(acc[mt][nt][2], acc[mt][nt][3]);
                }
            }
        }
        __syncthreads();

        // LSTM cell: one per thread
        {
            float gi = gs0[cb * 32 + chl]      + gs0[(cb + 64) * 32 + chl]
                     + gs1[cb * 32 + chl]      + gs1[(cb + 64) * 32 + chl]      + pr0;
            float gf = gs0[cb * 32 + 8 + chl]  + gs0[(cb + 64) * 32 + 8 + chl]
                     + gs1[cb * 32 + 8 + chl]  + gs1[(cb + 64) * 32 + 8 + chl]  + pr1;
            float gg = gs0[cb * 32 + 16 + chl] + gs0[(cb + 64) * 32 + 16 + chl]
                     + gs1[cb * 32 + 16 + chl] + gs1[(cb + 64) * 32 + 16 + chl] + pr2;
            float go = gs0[cb * 32 + 24 + chl] + gs0[(cb + 64) * 32 + 24 + chl]
                     + gs1[cb * 32 + 24 + chl] + gs1[(cb + 64) * 32 + 24 + chl] + pr3;
            float si = sigm(gi), sf = sigm(gf), so = sigm(go);
            float tg = tanh_f(gg);
            float cn = sf * creg + si * tg;
            creg = cn;
            float hn = so * tanh_f(cn);

            long long srow = (long long)cb * T + t;
            __nv_bfloat16 hi = __float2bfloat16(hn);
            __nv_bfloat16 lo = __float2bfloat16(hn - __bfloat162float(hi));
            hout[cb * 1024 + chg] = hi;
            hout[(cb + 64) * 1024 + chg] = lo;
            if (spk) {
                spk[srow * 1024 + chg] = hi;
                spk[splane + srow * 1024 + chg] = lo;
            }
        }

        // publish: h(t) chunk ready (+1 from this block; 8 blocks per chunk)
        __syncthreads();
        if (tid == 0) {
            unsigned dummy;
            asm volatile("atom.add.release.gpu.u32 %0, [%1], 1;"
                         : "=r"(dummy) : "l"(myflag) : "memory");
        }
    }

    cstate[cb * 1024 + chg] = creg;
}

// ----------------------- softmax over 128 -----------------------
__global__ void softmax128(float* __restrict__ s) {
    int row = blockIdx.x;
    float* p = s + (long long)row * 128;
    int t = threadIdx.x;
    __shared__ float red[4];
    float v = p[t];
    float m = v;
#pragma unroll
    for (int o = 16; o; o >>= 1) m = fmaxf(m, __shfl_xor_sync(0xffffffffu, m, o));
    if ((t & 31) == 0) red[t >> 5] = m;
    __syncthreads();
    m = fmaxf(fmaxf(red[0], red[1]), fmaxf(red[2], red[3]));
    __syncthreads();
    float e = __expf(v - m);
    float sum = e;
#pragma unroll
    for (int o = 16; o; o >>= 1) sum += __shfl_xor_sync(0xffffffffu, sum, o);
    if ((t & 31) == 0) red[t >> 5] = sum;
    __syncthreads();
    sum = red[0] + red[1] + red[2] + red[3];
    p[t] = e / sum;
}

// ----------------------- ctx = attn @ src_emb -> d_out (s-outer, 16-row tiles) -----------------------
__global__ void __launch_bounds__(256) ctx_kernel(const float* __restrict__ attn,
                                                  const float* __restrict__ emb,
                                                  float* __restrict__ out) {
    int q = blockIdx.x, b = blockIdx.y;
    int t0 = q * 16;
    int nt = (t0 + 16 <= 63) ? 16 : (63 - t0);
    __shared__ float a[16][128];
    int tid = threadIdx.x;
    for (int i = tid; i < nt * 128; i += 256) {
        int tt = i >> 7, ss = i & 127;
        a[tt][ss] = attn[((long long)b * 63 + t0 + tt) * 128 + ss];
    }
    __syncthreads();
    const float* e = emb + (long long)b * 128 * 512;
    int n0 = tid, n1 = tid + 256;
    float acc0[16], acc1[16];
#pragma unroll
    for (int i = 0; i < 16; i++) { acc0[i] = 0.f; acc1[i] = 0.f; }
    for (int s = 0; s < 128; s++) {
        float e0 = e[(long long)s * 512 + n0];
        float e1 = e[(long long)s * 512 + n1];
#pragma unroll
        for (int i = 0; i < 16; i++) {
            float av = a[i][s];
            acc0[i] += av * e0;
            acc1[i] += av * e1;
        }
    }
    for (int i = 0; i < nt; i++) {
        float* o = out + ((long long)b * 64 + (t0 + i + 1)) * 512;
        o[n0] = acc0[i];
        o[n1] = acc1[i];
    }
}

// ----------------------- finalize -----------------------
__global__ void finalize(const float* __restrict__ attn, float* __restrict__ out) {
    int i = blockIdx.x * 256 + threadIdx.x;
    if (i < 64 * 512) {
        int b = i >> 9, n = i & 511;
        out[((long long)b * 64) * 512 + n] = 0.f;
    }
    if (i < 64 * 128) {
        int b = i >> 7, s = i & 127;
        out[64LL * 64 * 512 + b * 128 + s] = attn[((long long)b * 63 + 62) * 128 + s];
    }
}

// ----------------------- host -----------------------
static float* addr_of(const void* symbol) {
    void* p = nullptr;
    cudaGetSymbolAddress(&p, symbol);
    return (float*)p;
}

extern "C" void kernel_launch(void* const* d_in, const int* in_sizes, int n_in,
                              void* d_out, int out_size) {
    const int*   src  = (const int*)d_in[0];
    const int*   trg  = (const int*)d_in[1];
    const float* srct = (const float*)d_in[2];
    const float* trgt = (const float*)d_in[3];
    const float* fcW  = (const float*)d_in[4];
    const float* fcb  = (const float*)d_in[5];
    const float* eW0  = (const float*)d_in[6];
    const float* eU0  = (const float*)d_in[7];
    const float* eb0  = (const float*)d_in[8];
    const float* ebb0 = (const float*)d_in[9];
    const float* eW1  = (const float*)d_in[10];
    const float* eU1  = (const float*)d_in[11];
    const float* eb1  = (const float*)d_in[12];
    const float* ebb1 = (const float*)d_in[13];
    const float* dW0  = (const float*)d_in[14];
    const float* dU0  = (const float*)d_in[15];
    const float* db0  = (const float*)d_in[16];
    const float* dbb0 = (const float*)d_in[17];
    const float* dW1  = (const float*)d_in[18];
    const float* dU1  = (const float*)d_in[19];
    const float* db1  = (const float*)d_in[20];
    const float* dbb1 = (const float*)d_in[21];
    float* out = (float*)d_out;

    float* srcemb = addr_of(g_srcemb);
    float* pre    = addr_of(g_pre);
    float* preds  = addr_of(g_preds);
    float* scores = addr_of(g_scores);
    float* cst    = addr_of(g_cstate);

    __nv_bfloat16* wpk    = (__nv_bfloat16*)addr_of(g_wpk);
    __nv_bfloat16* wihpk  = (__nv_bfloat16*)addr_of(g_wihpk);
    __nv_bfloat16* fcpk   = (__nv_bfloat16*)addr_of(g_fcpk);
    __nv_bfloat16* srcpk  = (__nv_bfloat16*)addr_of(g_srcpk);
    __nv_bfloat16* decpk  = (__nv_bfloat16*)addr_of(g_decpk);
    __nv_bfloat16* seqApk = (__nv_bfloat16*)addr_of(g_seqApk);
    __nv_bfloat16* dseqApk= (__nv_bfloat16*)addr_of(g_dseqApk);
    __nv_bfloat16* dseqBpk= (__nv_bfloat16*)addr_of(g_dseqBpk);
    __nv_bfloat16* hpk    = (__nv_bfloat16*)addr_of(g_hpk);

    const long long WPK_L  = 128LL * 64 * 1024;
    const long long WIH_L  = 2LL * 4096 * 1024;
    const long long HPK_P  = 128LL * 1024;
    __nv_bfloat16* hA0 = hpk,             * hA1 = hpk + HPK_P;
    __nv_bfloat16* hB0 = hpk + 2 * HPK_P, * hB1 = hpk + 3 * HPK_P;

    float* c0 = cst;
    float* c1 = cst + 64 * 1024;

    cudaFuncSetAttribute(lstm_layer_mma, cudaFuncAttributeMaxDynamicSharedMemorySize, LSTM_SMEM);
    cudaFuncSetAttribute(gemm_bf16, cudaFuncAttributeMaxDynamicSharedMemorySize, 2 * GB_STG);

    zero_init<<<512, 256>>>();
    prep_w4<<<dim3(128, 4), 256>>>(eU0, eU1, dU0, dU1);
    prep_all<<<dim3(1024, 5), 256>>>(eW0, eW1, dW0, dW1, fcW);
    gather_src<<<8192, 128>>>(src, srct, srcemb, srcpk);
    gather_dec<<<4032, 128>>>(trg, trgt, decpk);

    // ---- encoder layer 0 ----
    gemm_bf16<<<dim3(64, 64), 256, 2 * GB_STG>>>(srcpk, wihpk + 0 * WIH_L, eb0, ebb0,
                                                 pre, 8192, 4096, 512);
    lstm_layer_mma<<<128, 512, LSTM_SMEM>>>(pre, wpk + 0 * WPK_L, hA0, hA1, c0,
                                            seqApk, 8192LL * 1024, 128, 0);
    // ---- encoder layer 1 ----
    gemm_bf16<<<dim3(64, 64), 256, 2 * GB_STG>>>(seqApk, wihpk + 1 * WIH_L, eb1, ebb1,
                                                 pre, 8192, 4096, 1024);
    lstm_layer_mma<<<128, 512, LSTM_SMEM>>>(pre, wpk + 1 * WPK_L, hB0, hB1, c1,
                                            nullptr, 0, 128, 1);
    // ---- decoder layer 0 (chain A continues) ----
    gemm_bf16<<<dim3(64, 32), 256, 2 * GB_STG>>>(decpk, wihpk + 2 * WIH_L, db0, dbb0,
                                                 pre, 4032, 4096, 512);
    lstm_layer_mma<<<128, 512, LSTM_SMEM>>>(pre, wpk + 2 * WPK_L, hA0, hA1, c0,
                                            dseqApk, 4032LL * 1024, 63, 2);
    // ---- decoder layer 1 (chain B continues) ----
    gemm_bf16<<<dim3(64, 32), 256, 2 * GB_STG>>>(dseqApk, wihpk + 3 * WIH_L, db1, dbb1,
                                                 pre, 4032, 4096, 1024);
    lstm_layer_mma<<<128, 512, LSTM_SMEM>>>(pre, wpk + 3 * WPK_L, hB0, hB1, c1,
                                            dseqBpk, 4032LL * 1024, 63, 3);

    // ---- fc (bf16 HMMA) ----
    gemm_bf16<<<dim3(8, 32), 256, 2 * GB_STG>>>(dseqBpk, fcpk, fcb, nullptr,
                                                preds, 4032, 512, 1024);

    // ---- attention ----
    float alpha = 1.f / sqrtf(512.f);
    gemm_abt<<<dim3(2, 1, 64), 256>>>(preds, srcemb, nullptr, nullptr, scores,
                                      63, 128, 512, alpha,
                                      (long long)63 * 512, (long long)128 * 512, (long long)63 * 128);
    softmax128<<<4032, 128>>>(scores);
    ctx_kernel<<<dim3(4, 64), 256>>>(scores, srcemb, out);
    finalize<<<128, 256>>>(scores, out);
}

// round 14
// speedup vs baseline: 1.0874x; 1.0874x over previous
#include <cuda_runtime.h>
#include <cuda_bf16.h>
#include <math.h>
#include <stdint.h>

// ----------------------- problem dims -----------------------
// B=64, S_SRC=128, T_TRG=64 -> TDEC=63, E=512, H=1024, 4H=4096, NL=2
// SOS=1, SCALE=sqrt(512)

typedef unsigned long long u64;

#define FMA2(acc, a, b) asm("fma.rn.f32x2 %0, %1, %2, %3;" : "=l"(acc) : "l"(a), "l"(b), "l"(acc))

__device__ __forceinline__ float psum(u64 v) {
    float lo, hi;
    asm("mov.b64 {%0,%1}, %2;" : "=f"(lo), "=f"(hi) : "l"(v));
    return lo + hi;
}

__device__ __forceinline__ void cp16(unsigned dst, const void* src) {
    asm volatile("cp.async.cg.shared.global [%0], [%1], 16;" :: "r"(dst), "l"(src));
}
#define CP_COMMIT() asm volatile("cp.async.commit_group;")

__device__ __forceinline__ void ldsm4(unsigned* r, uint32_t addr) {
    asm volatile("ldmatrix.sync.aligned.m8n8.x4.shared.b16 {%0,%1,%2,%3}, [%4];"
                 : "=r"(r[0]), "=r"(r[1]), "=r"(r[2]), "=r"(r[3]) : "r"(addr));
}

__device__ __forceinline__ void mma16816(float* d, const unsigned* a, const unsigned* b) {
    asm volatile(
        "mma.sync.aligned.m16n8k16.row.col.f32.bf16.bf16.f32 "
        "{%0,%1,%2,%3}, {%4,%5,%6,%7}, {%8,%9}, {%0,%1,%2,%3};"
        : "+f"(d[0]), "+f"(d[1]), "+f"(d[2]), "+f"(d[3])
        : "r"(a[0]), "r"(a[1]), "r"(a[2]), "r"(a[3]), "r"(b[0]), "r"(b[1]));
}

__device__ __forceinline__ float sigm(float x) {
    float e = __expf(-x);
    return __fdividef(1.f, 1.f + e);
}
__device__ __forceinline__ float tanh_f(float x) {
    float xx = fminf(fmaxf(x, -30.f), 30.f);
    float e = __expf(-2.f * xx);
    return __fdividef(1.f - e, 1.f + e);
}

__device__ __forceinline__ void poll_flag(const unsigned* f, unsigned target) {
    unsigned v;
    do {
        asm volatile("ld.acquire.gpu.u32 %0, [%1];" : "=r"(v) : "l"(f) : "memory");
        if (v >= target) break;
        __nanosleep(16);
    } while (true);
}

// ----------------------- device scratch (no allocation) -----------------------
__device__ float g_srcemb[8192 * 512];
__device__ float g_pre[8192 * 4096];
__device__ float g_preds[4032 * 512];
__device__ float g_scores[4032 * 128];
__device__ float g_cstate[2 * 64 * 1024];
__device__ __nv_bfloat16 g_wpk[4][128 * 64 * 1024];
__device__ __nv_bfloat16 g_wihpk[4][2 * 4096 * 1024];
__device__ __nv_bfloat16 g_fcpk[2 * 512 * 1024];
__device__ __nv_bfloat16 g_srcpk[2 * 8192 * 512];
__device__ __nv_bfloat16 g_decpk[2 * 4032 * 512];
__device__ __nv_bfloat16 g_seqApk[2 * 8192 * 1024];
__device__ __nv_bfloat16 g_dseqApk[2 * 4032 * 1024];
__device__ __nv_bfloat16 g_dseqBpk[2 * 4032 * 1024];
__device__ __nv_bfloat16 g_hpk[2][2][128 * 1024];
// per-chunk h-ready flags: [layer][chunk][pad to 32B]
__device__ unsigned g_hflag[4][16][8];

// ----------------------- init -----------------------
__global__ void zero_init() {
    int i = blockIdx.x * 256 + threadIdx.x;
    if (i < 2 * 64 * 1024) g_cstate[i] = 0.f;
    if (i < 128 * 1024 / 2) {
        ((uint32_t*)g_hpk[0][0])[i] = 0u;
        ((uint32_t*)g_hpk[1][0])[i] = 0u;
    }
    if (i < 4 * 16 * 8) ((unsigned*)g_hflag)[i] = 0u;
}

// ----------------------- Whh -> packed bf16 hi/lo -----------------------
__global__ void prep_w4(const float* __restrict__ w0, const float* __restrict__ w1,
                        const float* __restrict__ w2, const float* __restrict__ w3) {
    int l = blockIdx.y;
    const float* Whh = (l == 0) ? w0 : (l == 1) ? w1 : (l == 2) ? w2 : w3;
    __nv_bfloat16* dst0 = &g_wpk[l][0];
    int bx = blockIdx.x >> 2;            // 128 W-slices
    int quarter = blockIdx.x & 3;
    __nv_bfloat16* dst = dst0 + ((long long)bx << 16);
    int i0 = quarter * 16384;
    for (int i = i0 + threadIdx.x; i < i0 + 16384; i += 256) {
        int r = i >> 10, k = i & 1023;
        int part = r >> 5, rr = r & 31;
        int grow = (rr >> 3) * 1024 + bx * 8 + (rr & 7);
        float v = Whh[(long long)grow * 1024 + k];
        __nv_bfloat16 hi = __float2bfloat16(v);
        if (part == 0) dst[i] = hi;
        else dst[i] = __float2bfloat16(v - __bfloat162float(hi));
    }
}

// ----------------------- all Wih + fcW -> bf16 hi/lo planes (one launch) -----------------------
__global__ void prep_all(const float* __restrict__ w0, const float* __restrict__ w1,
                         const float* __restrict__ w2, const float* __restrict__ w3,
                         const float* __restrict__ w4) {
    int j = blockIdx.y;
    const float* W;
    __nv_bfloat16* d;
    long long n;
    if (j == 0)      { W = w0; d = &g_wihpk[0][0]; n = 4096LL * 512; }
    else if (j == 1) { W = w1; d = &g_wihpk[1][0]; n = 4096LL * 1024; }
    else if (j == 2) { W = w2; d = &g_wihpk[2][0]; n = 4096LL * 512; }
    else if (j == 3) { W = w3; d = &g_wihpk[3][0]; n = 4096LL * 1024; }
    else             { W = w4; d = &g_fcpk[0];     n = 512LL * 1024; }
    for (long long i = blockIdx.x * 256 + threadIdx.x; i < n; i += (long long)gridDim.x * 256) {
        float v = W[i];
        __nv_bfloat16 hi = __float2bfloat16(v);
        d[i] = hi;
        d[n + i] = __float2bfloat16(v - __bfloat162float(hi));
    }
}

// ----------------------- embedding gathers -----------------------
__global__ void gather_src(const int* __restrict__ src, const float* __restrict__ tab,
                           float* __restrict__ out, __nv_bfloat16* __restrict__ pk) {
    int row = blockIdx.x;
    int tok = src[row];
    const float4* r = (const float4*)(tab + (long long)tok * 512);
    float4 v = r[threadIdx.x];
    ((float4*)(out + (long long)row * 512))[threadIdx.x] = v;
    const long long PL = 8192LL * 512;
    __nv_bfloat16 hx = __float2bfloat16(v.x), hy = __float2bfloat16(v.y);
    __nv_bfloat16 hz = __float2bfloat16(v.z), hw = __float2bfloat16(v.w);
    long long o = (long long)row * 512 + threadIdx.x * 4;
    pk[o] = hx; pk[o + 1] = hy; pk[o + 2] = hz; pk[o + 3] = hw;
    pk[PL + o]     = __float2bfloat16(v.x - __bfloat162float(hx));
    pk[PL + o + 1] = __float2bfloat16(v.y - __bfloat162float(hy));
    pk[PL + o + 2] = __float2bfloat16(v.z - __bfloat162float(hz));
    pk[PL + o + 3] = __float2bfloat16(v.w - __bfloat162float(hw));
}

__global__ void gather_dec(const int* __restrict__ trg, const float* __restrict__ tab,
                           __nv_bfloat16* __restrict__ pk) {
    int row = blockIdx.x;
    int b = row / 63, t = row % 63;
    int tok = (t == 0) ? 1 : trg[b * 64 + t];
    const float4* r = (const float4*)(tab + (long long)tok * 512);
    float4 v = r[threadIdx.x];
    const long long PL = 4032LL * 512;
    __nv_bfloat16 hx = __float2bfloat16(v.x), hy = __float2bfloat16(v.y);
    __nv_bfloat16 hz = __float2bfloat16(v.z), hw = __float2bfloat16(v.w);
    long long o = (long long)row * 512 + threadIdx.x * 4;
    pk[o] = hx; pk[o + 1] = hy; pk[o + 2] = hz; pk[o + 3] = hw;
    pk[PL + o]     = __float2bfloat16(v.x - __bfloat162float(hx));
    pk[PL + o + 1] = __float2bfloat16(v.y - __bfloat162float(hy));
    pk[PL + o + 2] = __float2bfloat16(v.z - __bfloat162float(hz));
    pk[PL + o + 3] = __float2bfloat16(v.w - __bfloat162float(hw));
}

// ----------------------- bf16 HMMA GEMM: C = A@W^T + b1 + b2 -----------------------
#define GB_STG 49152
__global__ void __launch_bounds__(256, 2) gemm_bf16(
    const __nv_bfloat16* __restrict__ apk,
    const __nv_bfloat16* __restrict__ wpk,
    const float* __restrict__ b1, const float* __restrict__ b2,
    float* __restrict__ C, int M, int N, int K)
{
    extern __shared__ __align__(128) char smem[];
    uint32_t sbase = (uint32_t)__cvta_generic_to_shared(smem);
    int tid = threadIdx.x, lane = tid & 31, w = tid >> 5;
    int mg = w & 3, ng = w >> 2;
    int m0 = blockIdx.y * 128, n0 = blockIdx.x * 64;
    long long Kb = (long long)K * 2;
    const char* ah = (const char*)apk;
    const char* al = ah + (long long)M * K * 2;
    const char* bh = (const char*)wpk;
    const char* bl = bh + (long long)N * K * 2;
    int nch = K >> 6;

    int arow = tid >> 3, acol = tid & 7;
#pragma unroll
    for (int s = 0; s < 2; s++) {
        uint32_t base = sbase + s * GB_STG;
#pragma unroll
        for (int i = 0; i < 4; i++) {
            int row = arow + i * 32;
            int gr = m0 + row; if (gr >= M) gr = M - 1;
            uint32_t d = row * 128 + ((acol ^ (row & 7)) << 4);
            cp16(base + d, ah + gr * Kb + s * 128 + acol * 16);
            cp16(base + 16384 + d, al + gr * Kb + s * 128 + acol * 16);
        }
#pragma unroll
        for (int i = 0; i < 2; i++) {
            int row = arow + i * 32;
            if (row < 64) {
                uint32_t d = row * 128 + ((acol ^ (row & 7)) << 4);
                cp16(base + 32768 + d, bh + (long long)(n0 + row) * Kb + s * 128 + acol * 16);
                cp16(base + 40960 + d, bl + (long long)(n0 + row) * Kb + s * 128 + acol * 16);
            }
        }
        CP_COMMIT();
    }

    int matA = lane >> 3;
    int rAoff = (matA & 1) * 8 + (lane & 7);
    int kselA = matA >> 1;
    int rBoff = ((lane >> 4) & 1) * 8 + (lane & 7);
    int kselB = (lane >> 3) & 1;

    float acc[2][4][4];
#pragma unroll
    for (int a = 0; a < 2; a++)
#pragma unroll
        for (int j = 0; j < 4; j++)
#pragma unroll
            for (int k = 0; k < 4; k++) acc[a][j][k] = 0.f;

    for (int c = 0; c < nch; c++) {
        asm volatile("cp.async.wait_group 1;" ::: "memory");
        __syncthreads();

        uint32_t aH = sbase + (c & 1) * GB_STG;
        uint32_t aL = aH + 16384, bH = aH + 32768, bL = aH + 40960;
#pragma unroll
        for (int kt = 0; kt < 4; kt++) {
            unsigned afh[2][4], afl[2][4];
#pragma unroll
            for (int mt = 0; mt < 2; mt++) {
                int row = 32 * mg + 16 * mt + rAoff;
                int col = kt * 2 + kselA;
                uint32_t sw = row * 128 + ((col ^ (row & 7)) << 4);
                ldsm4(afh[mt], aH + sw);
                ldsm4(afl[mt], aL + sw);
            }
#pragma unroll
            for (int bt = 0; bt < 2; bt++) {
                int row = 32 * ng + 16 * bt + rBoff;
                int col = kt * 2 + kselB;
                uint32_t sw = row * 128 + ((col ^ (row & 7)) << 4);
                unsigned bfh[4], bfl[4];
                ldsm4(bfh, bH + sw);
                ldsm4(bfl, bL + sw);
#pragma unroll
                for (int mt = 0; mt < 2; mt++) {
                    mma16816(acc[mt][2 * bt + 0], afh[mt], bfh + 0);
                    mma16816(acc[mt][2 * bt + 1], afh[mt], bfh + 2);
                    mma16816(acc[mt][2 * bt + 0], afh[mt], bfl + 0);
                    mma16816(acc[mt][2 * bt + 1], afh[mt], bfl + 2);
                    mma16816(acc[mt][2 * bt + 0], afl[mt], bfh + 0);
                    mma16816(acc[mt][2 * bt + 1], afl[mt], bfh + 2);
                }
            }
        }
        __syncthreads();

        int p2 = c + 2;
        if (p2 < nch) {
            uint32_t base = sbase + (c & 1) * GB_STG;
#pragma unroll
            for (int i = 0; i < 4; i++) {
                int row = arow + i * 32;
                int gr = m0 + row; if (gr >= M) gr = M - 1;
                uint32_t d = row * 128 + ((acol ^ (row & 7)) << 4);
                cp16(base + d, ah + gr * Kb + p2 * 128 + acol * 16);
                cp16(base + 16384 + d, al + gr * Kb + p2 * 128 + acol * 16);
            }
#pragma unroll
            for (int i = 0; i < 2; i++) {
                int row = arow + i * 32;
                if (row < 64) {
                    uint32_t d = row * 128 + ((acol ^ (row & 7)) << 4);
                    cp16(base + 32768 + d, bh + (long long)(n0 + row) * Kb + p2 * 128 + acol * 16);
                    cp16(base + 40960 + d, bl + (long long)(n0 + row) * Kb + p2 * 128 + acol * 16);
                }
            }
        }
        CP_COMMIT();
    }

#pragma unroll
    for (int mt = 0; mt < 2; mt++) {
        int r0 = 32 * mg + 16 * mt + (lane >> 2);
#pragma unroll
        for (int j = 0; j < 4; j++) {
            int col = n0 + 32 * ng + 8 * j + (lane & 3) * 2;
            float bb0 = b1[col], bb1 = b1[col + 1];
            if (b2) { bb0 += b2[col]; bb1 += b2[col + 1]; }
            int gm = m0 + r0;
            if (gm < M) {
                float2 v = make_float2(acc[mt][j][0] + bb0, acc[mt][j][1] + bb1);
                *(float2*)&C[(long long)gm * N + col] = v;
            }
            if (gm + 8 < M) {
                float2 v = make_float2(acc[mt][j][2] + bb0, acc[mt][j][3] + bb1);
                *(float2*)&C[(long long)(gm + 8) * N + col] = v;
            }
        }
    }
}

// ----------------------- fp32 f32x2 GEMM (attention scores) -----------------------
__global__ void __launch_bounds__(256, 1) gemm_abt(
    const float* __restrict__ A, const float* __restrict__ W,
    const float* __restrict__ b1, const float* __restrict__ b2,
    float* __restrict__ C,
    int M, int N, int K, float alpha,
    long long strideA, long long strideW, long long strideC)
{
    A += (long long)blockIdx.z * strideA;
    W += (long long)blockIdx.z * strideW;
    C += (long long)blockIdx.z * strideC;

    __shared__ __align__(16) float As[2][128][36];
    __shared__ __align__(16) float Bs[2][64][36];

    int tid = threadIdx.x;
    int m0 = blockIdx.y * 128;
    int n0 = blockIdx.x * 64;
    int ty = tid >> 4, tx = tid & 15;

    u64 acc[8][4];
#pragma unroll
    for (int i = 0; i < 8; i++)
#pragma unroll
        for (int j = 0; j < 4; j++) acc[i][j] = 0ull;

    float4 sa[4], sb[2];
    const float4 z4 = {0.f, 0.f, 0.f, 0.f};
    int nch = K >> 5;

#pragma unroll
    for (int r = 0; r < 4; r++) {
        int li = tid + r * 256;
        int m = li >> 3, kq = li & 7;
        sa[r] = (m0 + m < M) ? *(const float4*)&A[(long long)(m0 + m) * K + kq * 4] : z4;
    }
#pragma unroll
    for (int r = 0; r < 2; r++) {
        int li = tid + r * 256;
        int n = li >> 3, kq = li & 7;
        sb[r] = *(const float4*)&W[(long long)(n0 + n) * K + kq * 4];
    }
#pragma unroll
    for (int r = 0; r < 4; r++) {
        int li = tid + r * 256;
        int m = li >> 3, kq = li & 7;
        *(float4*)&As[0][m][kq * 4] = sa[r];
    }
#pragma unroll
    for (int r = 0; r < 2; r++) {
        int li = tid + r * 256;
        int n = li >> 3, kq = li & 7;
        *(float4*)&Bs[0][n][kq * 4] = sb[r];
    }
    __syncthreads();

    for (int c = 0; c < nch; c++) {
        int cur = c & 1;
        int kc = (c + 1) << 5;
        if (c + 1 < nch) {
#pragma unroll
            for (int r = 0; r < 4; r++) {
                int li = tid + r * 256;
                int m = li >> 3, kq = li & 7;
                sa[r] = (m0 + m < M) ? *(const float4*)&A[(long long)(m0 + m) * K + kc + kq * 4] : z4;
            }
#pragma unroll
            for (int r = 0; r < 2; r++) {
                int li = tid + r * 256;
                int n = li >> 3, kq = li & 7;
                sb[r] = *(const float4*)&W[(long long)(n0 + n) * K + kc + kq * 4];
            }
        }
#pragma unroll
        for (int q = 0; q < 8; q++) {
            int k = q * 4;
            ulonglong2 a[8], ww[4];
#pragma unroll
            for (int i = 0; i < 8; i++) a[i] = *(const ulonglong2*)&As[cur][ty + 16 * i][k];
#pragma unroll
            for (int j = 0; j < 4; j++) ww[j] = *(const ulonglong2*)&Bs[cur][tx + 16 * j][k];
#pragma unroll
            for (int i = 0; i < 8; i++)
#pragma unroll
                for (int j = 0; j < 4; j++) {
                    FMA2(acc[i][j], a[i].x, ww[j].x);
                    FMA2(acc[i][j], a[i].y, ww[j].y);
                }
        }
        if (c + 1 < nch) {
            int nb = cur ^ 1;
#pragma unroll
            for (int r = 0; r < 4; r++) {
                int li = tid + r * 256;
                int m = li >> 3, kq = li & 7;
                *(float4*)&As[nb][m][kq * 4] = sa[r];
            }
#pragma unroll
            for (int r = 0; r < 2; r++) {
                int li = tid + r * 256;
                int n = li >> 3, kq = li & 7;
                *(float4*)&Bs[nb][n][kq * 4] = sb[r];
            }
        }
        __syncthreads();
    }

#pragma unroll
    for (int i = 0; i < 8; i++) {
        int m = m0 + ty + 16 * i;
        if (m >= M) continue;
#pragma unroll
        for (int j = 0; j < 4; j++) {
            int n = n0 + tx + 16 * j;
            float v = psum(acc[i][j]) * alpha;
            if (b1) v += b1[n];
            if (b2) v += b2[n];
            C[(long long)m * N + n] = v;
        }
    }
}

// ----------------------- persistent HMMA LSTM layer (barrier-free, parallel polls) -----------------------
// SMEM: A ring 6x16KB @0 (gs0/gs1 overlay stages 0,1 at epilogue) | W 128KB @98304. Total 229376.
#define SA_OFF 0
#define SW_OFF 98304
#define LSTM_SMEM 229376

__global__ void __launch_bounds__(512, 1) lstm_layer_mma(
    const float* __restrict__ pre,
    const __nv_bfloat16* __restrict__ wpk,
    __nv_bfloat16* __restrict__ h0,
    __nv_bfloat16* __restrict__ h1,
    float* __restrict__ cstate,
    __nv_bfloat16* __restrict__ spk,
    long long splane,
    int T, int barid)
{
    extern __shared__ __align__(128) char smem[];
    uint32_t sbase = (uint32_t)__cvta_generic_to_shared(smem);

    int tid = threadIdx.x, lane = tid & 31;
    int wgid = tid >> 8;
    int w = (tid >> 5) & 7;
    int mg = (w & 1) | ((w >> 2) << 1);
    int ng = (w >> 1) & 1;
    int bx = blockIdx.x, hbase = bx * 8;

    unsigned (*flags)[8] = g_hflag[barid];
    unsigned* myflag = &g_hflag[barid][bx >> 3][0];

    const char* wsrc = (const char*)(wpk + ((long long)bx << 16));

    // load W slice once
#pragma unroll
    for (int i = 0; i < 16; i++) {
        int v = tid + i * 512;
        int ck = v >> 9;
        int rc = v & 511;
        int row = rc >> 3, col = rc & 7;
        cp16(sbase + SW_OFF + ck * 8192 + row * 128 + ((col ^ (row & 7)) << 4),
             wsrc + row * 2048 + ck * 128 + col * 16);
    }
    CP_COMMIT();
    asm volatile("cp.async.wait_group 0;" ::: "memory");
    __syncthreads();

    int matA = lane >> 3;
    int rAoff = (matA & 1) * 8 + (lane & 7);
    int kselA = matA >> 1;
    int rBoff = ((lane >> 4) & 1) * 8 + (lane & 7);
    int kselB = (lane >> 3) & 1;

    float* gs0 = (float*)(smem + SA_OFF);            // [128][32] overlays stage 0
    float* gs1 = (float*)(smem + SA_OFF + 16384);    // [128][32] overlays stage 1

    int cb = tid >> 3, chl = tid & 7;
    int chg = hbase + chl;
    float creg = cstate[cb * 1024 + chg];

    for (int t = 0; t < T; t++) {
        const char* asrc = (const char*)((t & 1) ? h1 : h0);
        __nv_bfloat16* hout = (t & 1) ? h0 : h1;
        unsigned target = 8u * (unsigned)t;

        long long prow = ((long long)cb * T + t) * 4096;
        float pr0 = pre[prow + chg];
        float pr1 = pre[prow + 1024 + chg];
        float pr2 = pre[prow + 2048 + chg];
        float pr3 = pre[prow + 3072 + chg];

        // poll chunks 0-3 ready (4 threads in parallel), then prologue loads
        if (t > 0 && tid < 4) poll_flag(&flags[tid][0], target);
        __syncthreads();

#pragma unroll
        for (int s = 0; s < 4; s++) {
#pragma unroll
            for (int i = 0; i < 2; i++) {
                int v = tid + i * 512, row = v >> 3, col = v & 7;
                cp16(sbase + SA_OFF + s * 16384 + row * 128 + ((col ^ (row & 7)) << 4),
                     asrc + row * 2048 + s * 128 + col * 16);
            }
            if (s & 1) CP_COMMIT();
        }

        float acc[2][2][4];
#pragma unroll
        for (int a = 0; a < 2; a++)
#pragma unroll
            for (int b = 0; b < 2; b++)
#pragma unroll
                for (int k = 0; k < 4; k++) acc[a][b][k] = 0.f;

        for (int p = 0; p < 8; p++) {
            asm volatile("cp.async.wait_group 1;" ::: "memory");
            int pn = p + 2;
            if (pn < 8 && t > 0 && tid < 2) poll_flag(&flags[2 * pn + tid][0], target);
            __syncthreads();

            if (pn < 8) {
#pragma unroll
                for (int s2 = 0; s2 < 2; s2++) {
                    int cc = 2 * pn + s2;
                    int st = cc % 6;
#pragma unroll
                    for (int i = 0; i < 2; i++) {
                        int v = tid + i * 512, row = v >> 3, col = v & 7;
                        cp16(sbase + SA_OFF + st * 16384 + row * 128 + ((col ^ (row & 7)) << 4),
                             asrc + row * 2048 + cc * 128 + col * 16);
                    }
                }
            }
            CP_COMMIT();

            int c = 2 * p + wgid;
            uint32_t aS = sbase + SA_OFF + (c % 6) * 16384;
            uint32_t bS = sbase + SW_OFF + c * 8192;
#pragma unroll
            for (int kt = 0; kt < 4; kt++) {
                unsigned af[2][4];
#pragma unroll
                for (int mt = 0; mt < 2; mt++) {
                    int row = 32 * mg + 16 * mt + rAoff;
                    int col = kt * 2 + kselA;
                    ldsm4(af[mt], aS + row * 128 + ((col ^ (row & 7)) << 4));
                }
#pragma unroll
                for (int pp = 0; pp < 2; pp++) {
                    if (pp == 1 && mg >= 2) break;
                    unsigned bf[4];
                    int row = 32 * pp + 16 * ng + rBoff;
                    int col = kt * 2 + kselB;
                    ldsm4(bf, bS + row * 128 + ((col ^ (row & 7)) << 4));
#pragma unroll
                    for (int mt = 0; mt < 2; mt++) {
                        mma16816(acc[mt][0], af[mt], bf + 0);
                        mma16816(acc[mt][1], af[mt], bf + 2);
                    }
                }
            }
        }

        // epilogue: each warpgroup writes its own gs region (stages 0,1 idle since pair 6)
        __syncthreads();
        {
            float* gsw = wgid ? gs1 : gs0;
#pragma unroll
            for (int mt = 0; mt < 2; mt++) {
                int row = 32 * mg + 16 * mt + (lane >> 2);
#pragma unroll
                for (int nt = 0; nt < 2; nt++) {
                    int col = 16 * ng + 8 * nt + (lane & 3) * 2;
                    *(float2*)&gsw[row * 32 + col] = make_float2(acc[mt][nt][0], acc[mt][nt][1]);
                    *(float2*)&gsw[(row + 8) * 32 + col] = make_float2(acc[mt][nt][2], acc[mt][nt][3]);
                }
            }
        }
        __syncthreads();

        // LSTM cell: one per thread
        {
            float gi = gs0[cb * 32 + chl]      + gs0[(cb + 64) * 32 + chl]
                     + gs1[cb * 32 + chl]      + gs1[(cb + 64) * 32 + chl]      + pr0;
            float gf = gs0[cb * 32 + 8 + chl]  + gs0[(cb + 64) * 32 + 8 + chl]
                     + gs1[cb * 32 + 8 + chl]  + gs1[(cb + 64) * 32 + 8 + chl]  + pr1;
            float gg = gs0[cb * 32 + 16 + chl] + gs0[(cb + 64) * 32 + 16 + chl]
                     + gs1[cb * 32 + 16 + chl] + gs1[(cb + 64) * 32 + 16 + chl] + pr2;
            float go = gs0[cb * 32 + 24 + chl] + gs0[(cb + 64) * 32 + 24 + chl]
                     + gs1[cb * 32 + 24 + chl] + gs1[(cb + 64) * 32 + 24 + chl] + pr3;
            float si = sigm(gi), sf = sigm(gf), so = sigm(go);
            float tg = tanh_f(gg);
            float cn = sf * creg + si * tg;
            creg = cn;
            float hn = so * tanh_f(cn);

            long long srow = (long long)cb * T + t;
            __nv_bfloat16 hi = __float2bfloat16(hn);
            __nv_bfloat16 lo = __float2bfloat16(hn - __bfloat162float(hi));
            hout[cb * 1024 + chg] = hi;
            hout[(cb + 64) * 1024 + chg] = lo;
            if (spk) {
                spk[srow * 1024 + chg] = hi;
                spk[splane + srow * 1024 + chg] = lo;
            }
        }

        // publish: h(t) chunk ready (+1 from this block; 8 blocks per chunk)
        __syncthreads();
        if (tid == 0) {
            unsigned dummy;
            asm volatile("atom.add.release.gpu.u32 %0, [%1], 1;"
                         : "=r"(dummy) : "l"(myflag) : "memory");
        }
    }

    cstate[cb * 1024 + chg] = creg;
}

// ----------------------- softmax over 128 -----------------------
__global__ void softmax128(float* __restrict__ s) {
    int row = blockIdx.x;
    float* p = s + (long long)row * 128;
    int t = threadIdx.x;
    __shared__ float red[4];
    float v = p[t];
    float m = v;
#pragma unroll
    for (int o = 16; o; o >>= 1) m = fmaxf(m, __shfl_xor_sync(0xffffffffu, m, o));
    if ((t & 31) == 0) red[t >> 5] = m;
    __syncthreads();
    m = fmaxf(fmaxf(red[0], red[1]), fmaxf(red[2], red[3]));
    __syncthreads();
    float e = __expf(v - m);
    float sum = e;
#pragma unroll
    for (int o = 16; o; o >>= 1) sum += __shfl_xor_sync(0xffffffffu, sum, o);
    if ((t & 31) == 0) red[t >> 5] = sum;
    __syncthreads();
    sum = red[0] + red[1] + red[2] + red[3];
    p[t] = e / sum;
}

// ----------------------- ctx = attn @ src_emb -> d_out (s-outer, 16-row tiles) -----------------------
__global__ void __launch_bounds__(256) ctx_kernel(const float* __restrict__ attn,
                                                  const float* __restrict__ emb,
                                                  float* __restrict__ out) {
    int q = blockIdx.x, b = blockIdx.y;
    int t0 = q * 16;
    int nt = (t0 + 16 <= 63) ? 16 : (63 - t0);
    __shared__ float a[16][128];
    int tid = threadIdx.x;
    for (int i = tid; i < nt * 128; i += 256) {
        int tt = i >> 7, ss = i & 127;
        a[tt][ss] = attn[((long long)b * 63 + t0 + tt) * 128 + ss];
    }
    __syncthreads();
    const float* e = emb + (long long)b * 128 * 512;
    int n0 = tid, n1 = tid + 256;
    float acc0[16], acc1[16];
#pragma unroll
    for (int i = 0; i < 16; i++) { acc0[i] = 0.f; acc1[i] = 0.f; }
    for (int s = 0; s < 128; s++) {
        float e0 = e[(long long)s * 512 + n0];
        float e1 = e[(long long)s * 512 + n1];
#pragma unroll
        for (int i = 0; i < 16; i++) {
            float av = a[i][s];
            acc0[i] += av * e0;
            acc1[i] += av * e1;
        }
    }
    for (int i = 0; i < nt; i++) {
        float* o = out + ((long long)b * 64 + (t0 + i + 1)) * 512;
        o[n0] = acc0[i];
        o[n1] = acc1[i];
    }
}

// ----------------------- finalize -----------------------
__global__ void finalize(const float* __restrict__ attn, float* __restrict__ out) {
    int i = blockIdx.x * 256 + threadIdx.x;
    if (i < 64 * 512) {
        int b = i >> 9, n = i & 511;
        out[((long long)b * 64) * 512 + n] = 0.f;
    }
    if (i < 64 * 128) {
        int b = i >> 7, s = i & 127;
        out[64LL * 64 * 512 + b * 128 + s] = attn[((long long)b * 63 + 62) * 128 + s];
    }
}

// ----------------------- host -----------------------
static float* addr_of(const void* symbol) {
    void* p = nullptr;
    cudaGetSymbolAddress(&p, symbol);
    return (float*)p;
}

extern "C" void kernel_launch(void* const* d_in, const int* in_sizes, int n_in,
                              void* d_out, int out_size) {
    const int*   src  = (const int*)d_in[0];
    const int*   trg  = (const int*)d_in[1];
    const float* srct = (const float*)d_in[2];
    const float* trgt = (const float*)d_in[3];
    const float* fcW  = (const float*)d_in[4];
    const float* fcb  = (const float*)d_in[5];
    const float* eW0  = (const float*)d_in[6];
    const float* eU0  = (const float*)d_in[7];
    const float* eb0  = (const float*)d_in[8];
    const float* ebb0 = (const float*)d_in[9];
    const float* eW1  = (const float*)d_in[10];
    const float* eU1  = (const float*)d_in[11];
    const float* eb1  = (const float*)d_in[12];
    const float* ebb1 = (const float*)d_in[13];
    const float* dW0  = (const float*)d_in[14];
    const float* dU0  = (const float*)d_in[15];
    const float* db0  = (const float*)d_in[16];
    const float* dbb0 = (const float*)d_in[17];
    const float* dW1  = (const float*)d_in[18];
    const float* dU1  = (const float*)d_in[19];
    const float* db1  = (const float*)d_in[20];
    const float* dbb1 = (const float*)d_in[21];
    float* out = (float*)d_out;

    float* srcemb = addr_of(g_srcemb);
    float* pre    = addr_of(g_pre);
    float* preds  = addr_of(g_preds);
    float* scores = addr_of(g_scores);
    float* cst    = addr_of(g_cstate);

    __nv_bfloat16* wpk    = (__nv_bfloat16*)addr_of(g_wpk);
    __nv_bfloat16* wihpk  = (__nv_bfloat16*)addr_of(g_wihpk);
    __nv_bfloat16* fcpk   = (__nv_bfloat16*)addr_of(g_fcpk);
    __nv_bfloat16* srcpk  = (__nv_bfloat16*)addr_of(g_srcpk);
    __nv_bfloat16* decpk  = (__nv_bfloat16*)addr_of(g_decpk);
    __nv_bfloat16* seqApk = (__nv_bfloat16*)addr_of(g_seqApk);
    __nv_bfloat16* dseqApk= (__nv_bfloat16*)addr_of(g_dseqApk);
    __nv_bfloat16* dseqBpk= (__nv_bfloat16*)addr_of(g_dseqBpk);
    __nv_bfloat16* hpk    = (__nv_bfloat16*)addr_of(g_hpk);

    const long long WPK_L  = 128LL * 64 * 1024;
    const long long WIH_L  = 2LL * 4096 * 1024;
    const long long HPK_P  = 128LL * 1024;
    __nv_bfloat16* hA0 = hpk,             * hA1 = hpk + HPK_P;
    __nv_bfloat16* hB0 = hpk + 2 * HPK_P, * hB1 = hpk + 3 * HPK_P;

    float* c0 = cst;
    float* c1 = cst + 64 * 1024;

    cudaFuncSetAttribute(lstm_layer_mma, cudaFuncAttributeMaxDynamicSharedMemorySize, LSTM_SMEM);
    cudaFuncSetAttribute(gemm_bf16, cudaFuncAttributeMaxDynamicSharedMemorySize, 2 * GB_STG);

    zero_init<<<512, 256>>>();
    prep_w4<<<dim3(512, 4), 256>>>(eU0, eU1, dU0, dU1);
    prep_all<<<dim3(1024, 5), 256>>>(eW0, eW1, dW0, dW1, fcW);
    gather_src<<<8192, 128>>>(src, srct, srcemb, srcpk);
    gather_dec<<<4032, 128>>>(trg, trgt, decpk);

    // ---- encoder layer 0 ----
    gemm_bf16<<<dim3(64, 64), 256, 2 * GB_STG>>>(srcpk, wihpk + 0 * WIH_L, eb0, ebb0,
                                                 pre, 8192, 4096, 512);
    lstm_layer_mma<<<128, 512, LSTM_SMEM>>>(pre, wpk + 0 * WPK_L, hA0, hA1, c0,
                                            seqApk, 8192LL * 1024, 128, 0);
    // ---- encoder layer 1 ----
    gemm_bf16<<<dim3(64, 64), 256, 2 * GB_STG>>>(seqApk, wihpk + 1 * WIH_L, eb1, ebb1,
                                                 pre, 8192, 4096, 1024);
    lstm_layer_mma<<<128, 512, LSTM_SMEM>>>(pre, wpk + 1 * WPK_L, hB0, hB1, c1,
                                            nullptr, 0, 128, 1);
    // ---- decoder layer 0 (chain A continues) ----
    gemm_bf16<<<dim3(64, 32), 256, 2 * GB_STG>>>(decpk, wihpk + 2 * WIH_L, db0, dbb0,
                                                 pre, 4032, 4096, 512);
    lstm_layer_mma<<<128, 512, LSTM_SMEM>>>(pre, wpk + 2 * WPK_L, hA0, hA1, c0,
                                            dseqApk, 4032LL * 1024, 63, 2);
    // ---- decoder layer 1 (chain B continues) ----
    gemm_bf16<<<dim3(64, 32), 256, 2 * GB_STG>>>(dseqApk, wihpk + 3 * WIH_L, db1, dbb1,
                                                 pre, 4032, 4096, 1024);
    lstm_layer_mma<<<128, 512, LSTM_SMEM>>>(pre, wpk + 3 * WPK_L, hB0, hB1, c1,
                                            dseqBpk, 4032LL * 1024, 63, 3);

    // ---- fc (bf16 HMMA) ----
    gemm_bf16<<<dim3(8, 32), 256, 2 * GB_STG>>>(dseqBpk, fcpk, fcb, nullptr,
                                                preds, 4032, 512, 1024);

    // ---- attention ----
    float alpha = 1.f / sqrtf(512.f);
    gemm_abt<<<dim3(2, 1, 64), 256>>>(preds, srcemb, nullptr, nullptr, scores,
                                      63, 128, 512, alpha,
                                      (long long)63 * 512, (long long)128 * 512, (long long)63 * 128);
    softmax128<<<4032, 128>>>(scores);
    ctx_kernel<<<dim3(4, 64), 256>>>(scores, srcemb, out);
    finalize<<<128, 256>>>(scores, out);
}

// round 17
// speedup vs baseline: 1.1631x; 1.0696x over previous
#include <cuda_runtime.h>
#include <cuda_bf16.h>
#include <math.h>
#include <stdint.h>

// ----------------------- problem dims -----------------------
// B=64, S_SRC=128, T_TRG=64 -> TDEC=63, E=512, H=1024, 4H=4096, NL=2
// SOS=1, SCALE=sqrt(512)

typedef unsigned long long u64;

#define FMA2(acc, a, b) asm("fma.rn.f32x2 %0, %1, %2, %3;" : "=l"(acc) : "l"(a), "l"(b), "l"(acc))

__device__ __forceinline__ float psum(u64 v) {
    float lo, hi;
    asm("mov.b64 {%0,%1}, %2;" : "=f"(lo), "=f"(hi) : "l"(v));
    return lo + hi;
}

__device__ __forceinline__ void cp16(unsigned dst, const void* src) {
    asm volatile("cp.async.cg.shared.global [%0], [%1], 16;" :: "r"(dst), "l"(src));
}
#define CP_COMMIT() asm volatile("cp.async.commit_group;")

__device__ __forceinline__ void ldsm4(unsigned* r, uint32_t addr) {
    asm volatile("ldmatrix.sync.aligned.m8n8.x4.shared.b16 {%0,%1,%2,%3}, [%4];"
                 : "=r"(r[0]), "=r"(r[1]), "=r"(r[2]), "=r"(r[3]) : "r"(addr));
}

__device__ __forceinline__ void mma16816(float* d, const unsigned* a, const unsigned* b) {
    asm volatile(
        "mma.sync.aligned.m16n8k16.row.col.f32.bf16.bf16.f32 "
        "{%0,%1,%2,%3}, {%4,%5,%6,%7}, {%8,%9}, {%0,%1,%2,%3};"
        : "+f"(d[0]), "+f"(d[1]), "+f"(d[2]), "+f"(d[3])
        : "r"(a[0]), "r"(a[1]), "r"(a[2]), "r"(a[3]), "r"(b[0]), "r"(b[1]));
}

__device__ __forceinline__ float sigm(float x) {
    float e = __expf(-x);
    return __fdividef(1.f, 1.f + e);
}
__device__ __forceinline__ float tanh_f(float x) {
    float xx = fminf(fmaxf(x, -30.f), 30.f);
    float e = __expf(-2.f * xx);
    return __fdividef(1.f - e, 1.f + e);
}

// ----------------------- device scratch (no allocation) -----------------------
__device__ float g_srcemb[8192 * 512];
__device__ float g_pre[8192 * 4096];
__device__ float g_preds[4032 * 512];
__device__ float g_scores[4032 * 128];
__device__ float g_cstate[2 * 64 * 1024];
__device__ __nv_bfloat16 g_wpk[4][128 * 64 * 1024];
__device__ __nv_bfloat16 g_wihpk[4][2 * 4096 * 1024];
__device__ __nv_bfloat16 g_fcpk[2 * 512 * 1024];
__device__ __nv_bfloat16 g_srcpk[2 * 8192 * 512];
__device__ __nv_bfloat16 g_decpk[2 * 4032 * 512];
__device__ __nv_bfloat16 g_seqApk[2 * 8192 * 1024];
__device__ __nv_bfloat16 g_dseqApk[2 * 4032 * 1024];
__device__ __nv_bfloat16 g_dseqBpk[2 * 4032 * 1024];
__device__ __nv_bfloat16 g_hpk[2][2][128 * 1024];
// grid barrier
__device__ unsigned g_cnt[8];
__device__ unsigned g_rel[8];

// ----------------------- init -----------------------
__global__ void zero_init() {
    int i = blockIdx.x * 256 + threadIdx.x;
    if (i < 2 * 64 * 1024) g_cstate[i] = 0.f;
    if (i < 128 * 1024 / 2) {
        ((uint32_t*)g_hpk[0][0])[i] = 0u;
        ((uint32_t*)g_hpk[1][0])[i] = 0u;
    }
    if (i < 8) { g_cnt[i] = 0u; g_rel[i] = 0u; }
}

// ----------------------- grid barrier -----------------------
__device__ __forceinline__ void grid_bar(int id, int step, unsigned nb) {
    __syncthreads();
    if (threadIdx.x == 0) {
        unsigned* cnt = &g_cnt[id];
        unsigned* rel = &g_rel[id];
        unsigned target = nb * (unsigned)(step + 1);
        unsigned a;
        asm volatile("atom.add.release.gpu.u32 %0, [%1], 1;"
                     : "=r"(a) : "l"(cnt) : "memory");
        if (a == target - 1u) {
            asm volatile("st.release.gpu.u32 [%0], %1;" :: "l"(rel), "r"(target) : "memory");
        } else {
            unsigned v;
            do {
                asm volatile("ld.acquire.gpu.u32 %0, [%1];" : "=r"(v) : "l"(rel) : "memory");
                if (v >= target) break;
                __nanosleep(32);
            } while (true);
        }
    }
    __syncthreads();
}

// ----------------------- Whh -> packed bf16 hi/lo (quartered grid) -----------------------
__global__ void prep_w4(const float* __restrict__ w0, const float* __restrict__ w1,
                        const float* __restrict__ w2, const float* __restrict__ w3) {
    int l = blockIdx.y;
    const float* Whh = (l == 0) ? w0 : (l == 1) ? w1 : (l == 2) ? w2 : w3;
    __nv_bfloat16* dst0 = &g_wpk[l][0];
    int bx = blockIdx.x >> 2;
    int quarter = blockIdx.x & 3;
    __nv_bfloat16* dst = dst0 + ((long long)bx << 16);
    int i0 = quarter * 16384;
    for (int i = i0 + threadIdx.x; i < i0 + 16384; i += 256) {
        int r = i >> 10, k = i & 1023;
        int part = r >> 5, rr = r & 31;
        int grow = (rr >> 3) * 1024 + bx * 8 + (rr & 7);
        float v = Whh[(long long)grow * 1024 + k];
        __nv_bfloat16 hi = __float2bfloat16(v);
        if (part == 0) dst[i] = hi;
        else dst[i] = __float2bfloat16(v - __bfloat162float(hi));
    }
}

// ----------------------- all Wih + fcW -> bf16 hi/lo planes (one launch) -----------------------
__global__ void prep_all(const float* __restrict__ w0, const float* __restrict__ w1,
                         const float* __restrict__ w2, const float* __restrict__ w3,
                         const float* __restrict__ w4) {
    int j = blockIdx.y;
    const float* W;
    __nv_bfloat16* d;
    long long n;
    if (j == 0)      { W = w0; d = &g_wihpk[0][0]; n = 4096LL * 512; }
    else if (j == 1) { W = w1; d = &g_wihpk[1][0]; n = 4096LL * 1024; }
    else if (j == 2) { W = w2; d = &g_wihpk[2][0]; n = 4096LL * 512; }
    else if (j == 3) { W = w3; d = &g_wihpk[3][0]; n = 4096LL * 1024; }
    else             { W = w4; d = &g_fcpk[0];     n = 512LL * 1024; }
    for (long long i = blockIdx.x * 256 + threadIdx.x; i < n; i += (long long)gridDim.x * 256) {
        float v = W[i];
        __nv_bfloat16 hi = __float2bfloat16(v);
        d[i] = hi;
        d[n + i] = __float2bfloat16(v - __bfloat162float(hi));
    }
}

// ----------------------- merged embedding gathers -----------------------
__global__ void gather_all(const int* __restrict__ src, const int* __restrict__ trg,
                           const float* __restrict__ stab, const float* __restrict__ ttab,
                           float* __restrict__ out,
                           __nv_bfloat16* __restrict__ spk, __nv_bfloat16* __restrict__ dpk) {
    int row = blockIdx.x;                  // 0..12223
    if (row < 8192) {
        int tok = src[row];
        const float4* r = (const float4*)(stab + (long long)tok * 512);
        float4 v = r[threadIdx.x];
        ((float4*)(out + (long long)row * 512))[threadIdx.x] = v;
        const long long PL = 8192LL * 512;
        long long o = (long long)row * 512 + threadIdx.x * 4;
        __nv_bfloat16 hx = __float2bfloat16(v.x), hy = __float2bfloat16(v.y);
        __nv_bfloat16 hz = __float2bfloat16(v.z), hw = __float2bfloat16(v.w);
        spk[o] = hx; spk[o + 1] = hy; spk[o + 2] = hz; spk[o + 3] = hw;
        spk[PL + o]     = __float2bfloat16(v.x - __bfloat162float(hx));
        spk[PL + o + 1] = __float2bfloat16(v.y - __bfloat162float(hy));
        spk[PL + o + 2] = __float2bfloat16(v.z - __bfloat162float(hz));
        spk[PL + o + 3] = __float2bfloat16(v.w - __bfloat162float(hw));
    } else {
        int dr = row - 8192;               // 0..4031
        int b = dr / 63, t = dr % 63;
        int tok = (t == 0) ? 1 : trg[b * 64 + t];
        const float4* r = (const float4*)(ttab + (long long)tok * 512);
        float4 v = r[threadIdx.x];
        const long long PL = 4032LL * 512;
        long long o = (long long)dr * 512 + threadIdx.x * 4;
        __nv_bfloat16 hx = __float2bfloat16(v.x), hy = __float2bfloat16(v.y);
        __nv_bfloat16 hz = __float2bfloat16(v.z), hw = __float2bfloat16(v.w);
        dpk[o] = hx; dpk[o + 1] = hy; dpk[o + 2] = hz; dpk[o + 3] = hw;
        dpk[PL + o]     = __float2bfloat16(v.x - __bfloat162float(hx));
        dpk[PL + o + 1] = __float2bfloat16(v.y - __bfloat162float(hy));
        dpk[PL + o + 2] = __float2bfloat16(v.z - __bfloat162float(hz));
        dpk[PL + o + 3] = __float2bfloat16(v.w - __bfloat162float(hw));
    }
}

// ----------------------- bf16 HMMA GEMM: C = A@W^T + b1 + b2 -----------------------
#define GB_STG 49152
__global__ void __launch_bounds__(256, 2) gemm_bf16(
    const __nv_bfloat16* __restrict__ apk,
    const __nv_bfloat16* __restrict__ wpk,
    const float* __restrict__ b1, const float* __restrict__ b2,
    float* __restrict__ C, int M, int N, int K)
{
    extern __shared__ __align__(128) char smem[];
    uint32_t sbase = (uint32_t)__cvta_generic_to_shared(smem);
    int tid = threadIdx.x, lane = tid & 31, w = tid >> 5;
    int mg = w & 3, ng = w >> 2;
    int m0 = blockIdx.y * 128, n0 = blockIdx.x * 64;
    long long Kb = (long long)K * 2;
    const char* ah = (const char*)apk;
    const char* al = ah + (long long)M * K * 2;
    const char* bh = (const char*)wpk;
    const char* bl = bh + (long long)N * K * 2;
    int nch = K >> 6;

    int arow = tid >> 3, acol = tid & 7;
#pragma unroll
    for (int s = 0; s < 2; s++) {
        uint32_t base = sbase + s * GB_STG;
#pragma unroll
        for (int i = 0; i < 4; i++) {
            int row = arow + i * 32;
            int gr = m0 + row; if (gr >= M) gr = M - 1;
            uint32_t d = row * 128 + ((acol ^ (row & 7)) << 4);
            cp16(base + d, ah + gr * Kb + s * 128 + acol * 16);
            cp16(base + 16384 + d, al + gr * Kb + s * 128 + acol * 16);
        }
#pragma unroll
        for (int i = 0; i < 2; i++) {
            int row = arow + i * 32;
            if (row < 64) {
                uint32_t d = row * 128 + ((acol ^ (row & 7)) << 4);
                cp16(base + 32768 + d, bh + (long long)(n0 + row) * Kb + s * 128 + acol * 16);
                cp16(base + 40960 + d, bl + (long long)(n0 + row) * Kb + s * 128 + acol * 16);
            }
        }
        CP_COMMIT();
    }

    int matA = lane >> 3;
    int rAoff = (matA & 1) * 8 + (lane & 7);
    int kselA = matA >> 1;
    int rBoff = ((lane >> 4) & 1) * 8 + (lane & 7);
    int kselB = (lane >> 3) & 1;

    float acc[2][4][4];
#pragma unroll
    for (int a = 0; a < 2; a++)
#pragma unroll
        for (int j = 0; j < 4; j++)
#pragma unroll
            for (int k = 0; k < 4; k++) acc[a][j][k] = 0.f;

    for (int c = 0; c < nch; c++) {
        asm volatile("cp.async.wait_group 1;" ::: "memory");
        __syncthreads();

        uint32_t aH = sbase + (c & 1) * GB_STG;
        uint32_t aL = aH + 16384, bH = aH + 32768, bL = aH + 40960;
#pragma unroll
        for (int kt = 0; kt < 4; kt++) {
            unsigned afh[2][4], afl[2][4];
#pragma unroll
            for (int mt = 0; mt < 2; mt++) {
                int row = 32 * mg + 16 * mt + rAoff;
                int col = kt * 2 + kselA;
                uint32_t sw = row * 128 + ((col ^ (row & 7)) << 4);
                ldsm4(afh[mt], aH + sw);
                ldsm4(afl[mt], aL + sw);
            }
#pragma unroll
            for (int bt = 0; bt < 2; bt++) {
                int row = 32 * ng + 16 * bt + rBoff;
                int col = kt * 2 + kselB;
                uint32_t sw = row * 128 + ((col ^ (row & 7)) << 4);
                unsigned bfh[4], bfl[4];
                ldsm4(bfh, bH + sw);
                ldsm4(bfl, bL + sw);
#pragma unroll
                for (int mt = 0; mt < 2; mt++) {
                    mma16816(acc[mt][2 * bt + 0], afh[mt], bfh + 0);
                    mma16816(acc[mt][2 * bt + 1], afh[mt], bfh + 2);
                    mma16816(acc[mt][2 * bt + 0], afh[mt], bfl + 0);
                    mma16816(acc[mt][2 * bt + 1], afh[mt], bfl + 2);
                    mma16816(acc[mt][2 * bt + 0], afl[mt], bfh + 0);
                    mma16816(acc[mt][2 * bt + 1], afl[mt], bfh + 2);
                }
            }
        }
        __syncthreads();

        int p2 = c + 2;
        if (p2 < nch) {
            uint32_t base = sbase + (c & 1) * GB_STG;
#pragma unroll
            for (int i = 0; i < 4; i++) {
                int row = arow + i * 32;
                int gr = m0 + row; if (gr >= M) gr = M - 1;
                uint32_t d = row * 128 + ((acol ^ (row & 7)) << 4);
                cp16(base + d, ah + gr * Kb + p2 * 128 + acol * 16);
                cp16(base + 16384 + d, al + gr * Kb + p2 * 128 + acol * 16);
            }
#pragma unroll
            for (int i = 0; i < 2; i++) {
                int row = arow + i * 32;
                if (row < 64) {
                    uint32_t d = row * 128 + ((acol ^ (row & 7)) << 4);
                    cp16(base + 32768 + d, bh + (long long)(n0 + row) * Kb + p2 * 128 + acol * 16);
                    cp16(base + 40960 + d, bl + (long long)(n0 + row) * Kb + p2 * 128 + acol * 16);
                }
            }
        }
        CP_COMMIT();
    }

#pragma unroll
    for (int mt = 0; mt < 2; mt++) {
        int r0 = 32 * mg + 16 * mt + (lane >> 2);
#pragma unroll
        for (int j = 0; j < 4; j++) {
            int col = n0 + 32 * ng + 8 * j + (lane & 3) * 2;
            float bb0 = b1[col], bb1 = b1[col + 1];
            if (b2) { bb0 += b2[col]; bb1 += b2[col + 1]; }
            int gm = m0 + r0;
            if (gm < M) {
                float2 v = make_float2(acc[mt][j][0] + bb0, acc[mt][j][1] + bb1);
                *(float2*)&C[(long long)gm * N + col] = v;
            }
            if (gm + 8 < M) {
                float2 v = make_float2(acc[mt][j][2] + bb0, acc[mt][j][3] + bb1);
                *(float2*)&C[(long long)(gm + 8) * N + col] = v;
            }
        }
    }
}

// ----------------------- fp32 f32x2 GEMM (attention scores) -----------------------
__global__ void __launch_bounds__(256, 1) gemm_abt(
    const float* __restrict__ A, const float* __restrict__ W,
    const float* __restrict__ b1, const float* __restrict__ b2,
    float* __restrict__ C,
    int M, int N, int K, float alpha,
    long long strideA, long long strideW, long long strideC)
{
    A += (long long)blockIdx.z * strideA;
    W += (long long)blockIdx.z * strideW;
    C += (long long)blockIdx.z * strideC;

    __shared__ __align__(16) float As[2][128][36];
    __shared__ __align__(16) float Bs[2][64][36];

    int tid = threadIdx.x;
    int m0 = blockIdx.y * 128;
    int n0 = blockIdx.x * 64;
    int ty = tid >> 4, tx = tid & 15;

    u64 acc[8][4];
#pragma unroll
    for (int i = 0; i < 8; i++)
#pragma unroll
        for (int j = 0; j < 4; j++) acc[i][j] = 0ull;

    float4 sa[4], sb[2];
    const float4 z4 = {0.f, 0.f, 0.f, 0.f};
    int nch = K >> 5;

#pragma unroll
    for (int r = 0; r < 4; r++) {
        int li = tid + r * 256;
        int m = li >> 3, kq = li & 7;
        sa[r] = (m0 + m < M) ? *(const float4*)&A[(long long)(m0 + m) * K + kq * 4] : z4;
    }
#pragma unroll
    for (int r = 0; r < 2; r++) {
        int li = tid + r * 256;
        int n = li >> 3, kq = li & 7;
        sb[r] = *(const float4*)&W[(long long)(n0 + n) * K + kq * 4];
    }
#pragma unroll
    for (int r = 0; r < 4; r++) {
        int li = tid + r * 256;
        int m = li >> 3, kq = li & 7;
        *(float4*)&As[0][m][kq * 4] = sa[r];
    }
#pragma unroll
    for (int r = 0; r < 2; r++) {
        int li = tid + r * 256;
        int n = li >> 3, kq = li & 7;
        *(float4*)&Bs[0][n][kq * 4] = sb[r];
    }
    __syncthreads();

    for (int c = 0; c < nch; c++) {
        int cur = c & 1;
        int kc = (c + 1) << 5;
        if (c + 1 < nch) {
#pragma unroll
            for (int r = 0; r < 4; r++) {
                int li = tid + r * 256;
                int m = li >> 3, kq = li & 7;
                sa[r] = (m0 + m < M) ? *(const float4*)&A[(long long)(m0 + m) * K + kc + kq * 4] : z4;
            }
#pragma unroll
            for (int r = 0; r < 2; r++) {
                int li = tid + r * 256;
                int n = li >> 3, kq = li & 7;
                sb[r] = *(const float4*)&W[(long long)(n0 + n) * K + kc + kq * 4];
            }
        }
#pragma unroll
        for (int q = 0; q < 8; q++) {
            int k = q * 4;
            ulonglong2 a[8], ww[4];
#pragma unroll
            for (int i = 0; i < 8; i++) a[i] = *(const ulonglong2*)&As[cur][ty + 16 * i][k];
#pragma unroll
            for (int j = 0; j < 4; j++) ww[j] = *(const ulonglong2*)&Bs[cur][tx + 16 * j][k];
#pragma unroll
            for (int i = 0; i < 8; i++)
#pragma unroll
                for (int j = 0; j < 4; j++) {
                    FMA2(acc[i][j], a[i].x, ww[j].x);
                    FMA2(acc[i][j], a[i].y, ww[j].y);
                }
        }
        if (c + 1 < nch) {
            int nb = cur ^ 1;
#pragma unroll
            for (int r = 0; r < 4; r++) {
                int li = tid + r * 256;
                int m = li >> 3, kq = li & 7;
                *(float4*)&As[nb][m][kq * 4] = sa[r];
            }
#pragma unroll
            for (int r = 0; r < 2; r++) {
                int li = tid + r * 256;
                int n = li >> 3, kq = li & 7;
                *(float4*)&Bs[nb][n][kq * 4] = sb[r];
            }
        }
        __syncthreads();
    }

#pragma unroll
    for (int i = 0; i < 8; i++) {
        int m = m0 + ty + 16 * i;
        if (m >= M) continue;
#pragma unroll
        for (int j = 0; j < 4; j++) {
            int n = n0 + tx + 16 * j;
            float v = psum(acc[i][j]) * alpha;
            if (b1) v += b1[n];
            if (b2) v += b2[n];
            C[(long long)m * N + n] = v;
        }
    }
}

// ----------------------- persistent HMMA LSTM layer (grid_bar, 6-stage ring) -----------------------
// SMEM: A ring 6x16KB @0 (gs0/gs1 overlay stages 0,1 at epilogue) | W 128KB @98304. Total 229376.
#define SA_OFF 0
#define SW_OFF 98304
#define LSTM_SMEM 229376
#define NBLK 128u

__global__ void __launch_bounds__(512, 1) lstm_layer_mma(
    const float* __restrict__ pre,
    const __nv_bfloat16* __restrict__ wpk,
    __nv_bfloat16* __restrict__ h0,
    __nv_bfloat16* __restrict__ h1,
    float* __restrict__ cstate,
    __nv_bfloat16* __restrict__ spk,
    long long splane,
    int T, int barid)
{
    extern __shared__ __align__(128) char smem[];
    uint32_t sbase = (uint32_t)__cvta_generic_to_shared(smem);

    int tid = threadIdx.x, lane = tid & 31;
    int wgid = tid >> 8;
    int w = (tid >> 5) & 7;
    int mg = (w & 1) | ((w >> 2) << 1);
    int ng = (w >> 1) & 1;
    int bx = blockIdx.x, hbase = bx * 8;

    const char* wsrc = (const char*)(wpk + ((long long)bx << 16));

    // load W slice once
#pragma unroll
    for (int i = 0; i < 16; i++) {
        int v = tid + i * 512;
        int ck = v >> 9;
        int rc = v & 511;
        int row = rc >> 3, col = rc & 7;
        cp16(sbase + SW_OFF + ck * 8192 + row * 128 + ((col ^ (row & 7)) << 4),
             wsrc + row * 2048 + ck * 128 + col * 16);
    }
    CP_COMMIT();
    asm volatile("cp.async.wait_group 0;" ::: "memory");
    __syncthreads();

    int matA = lane >> 3;
    int rAoff = (matA & 1) * 8 + (lane & 7);
    int kselA = matA >> 1;
    int rBoff = ((lane >> 4) & 1) * 8 + (lane & 7);
    int kselB = (lane >> 3) & 1;

    float* gs0 = (float*)(smem + SA_OFF);            // [128][32] overlays stage 0
    float* gs1 = (float*)(smem + SA_OFF + 16384);    // [128][32] overlays stage 1

    int cb = tid >> 3, chl = tid & 7;
    int chg = hbase + chl;
    float creg = cstate[cb * 1024 + chg];

    for (int t = 0; t < T; t++) {
        const char* asrc = (const char*)((t & 1) ? h1 : h0);
        __nv_bfloat16* hout = (t & 1) ? h0 : h1;

        long long prow = ((long long)cb * T + t) * 4096;
        float pr0 = pre[prow + chg];
        float pr1 = pre[prow + 1024 + chg];
        float pr2 = pre[prow + 2048 + chg];
        float pr3 = pre[prow + 3072 + chg];

        // A prologue: pairs 0,1 -> stages 0..3 (one commit per pair)
#pragma unroll
        for (int s = 0; s < 4; s++) {
#pragma unroll
            for (int i = 0; i < 2; i++) {
                int v = tid + i * 512, row = v >> 3, col = v & 7;
                cp16(sbase + SA_OFF + s * 16384 + row * 128 + ((col ^ (row & 7)) << 4),
                     asrc + row * 2048 + s * 128 + col * 16);
            }
            if (s & 1) CP_COMMIT();
        }

        float acc[2][2][4];
#pragma unroll
        for (int a = 0; a < 2; a++)
#pragma unroll
            for (int b = 0; b < 2; b++)
#pragma unroll
                for (int k = 0; k < 4; k++) acc[a][b][k] = 0.f;

        for (int p = 0; p < 8; p++) {
            asm volatile("cp.async.wait_group 1;" ::: "memory");
            __syncthreads();

            // prefetch pair p+2 into stages (2p+4)%6, (2p+5)%6
            int pn = p + 2;
            if (pn < 8) {
#pragma unroll
                for (int s2 = 0; s2 < 2; s2++) {
                    int cc = 2 * pn + s2;
                    int st = cc % 6;
#pragma unroll
                    for (int i = 0; i < 2; i++) {
                        int v = tid + i * 512, row = v >> 3, col = v & 7;
                        cp16(sbase + SA_OFF + st * 16384 + row * 128 + ((col ^ (row & 7)) << 4),
                             asrc + row * 2048 + cc * 128 + col * 16);
                    }
                }
            }
            CP_COMMIT();

            int c = 2 * p + wgid;
            uint32_t aS = sbase + SA_OFF + (c % 6) * 16384;
            uint32_t bS = sbase + SW_OFF + c * 8192;
#pragma unroll
            for (int kt = 0; kt < 4; kt++) {
                unsigned af[2][4];
#pragma unroll
                for (int mt = 0; mt < 2; mt++) {
                    int row = 32 * mg + 16 * mt + rAoff;
                    int col = kt * 2 + kselA;
                    ldsm4(af[mt], aS + row * 128 + ((col ^ (row & 7)) << 4));
                }
#pragma unroll
                for (int pp = 0; pp < 2; pp++) {
                    if (pp == 1 && mg >= 2) break;   // 3-term: h_lo only x W_hi
                    unsigned bf[4];
                    int row = 32 * pp + 16 * ng + rBoff;
                    int col = kt * 2 + kselB;
                    ldsm4(bf, bS + row * 128 + ((col ^ (row & 7)) << 4));
#pragma unroll
                    for (int mt = 0; mt < 2; mt++) {
                        mma16816(acc[mt][0], af[mt], bf + 0);
                        mma16816(acc[mt][1], af[mt], bf + 2);
                    }
                }
            }
        }

        // epilogue: each warpgroup writes its own gs region (stages 0,1 idle since pair 6)
        __syncthreads();
        {
            float* gsw = wgid ? gs1 : gs0;
#pragma unroll
            for (int mt = 0; mt < 2; mt++) {
                int row = 32 * mg + 16 * mt + (lane >> 2);
#pragma unroll
                for (int nt = 0; nt < 2; nt++) {
                    int col = 16 * ng + 8 * nt + (lane & 3) * 2;
                    *(float2*)&gsw[row * 32 + col] = make_float2(acc[mt][nt][0], acc[mt][nt][1]);
                    *(float2*)&gsw[(row + 8) * 32 + col] = make_float2(acc[mt][nt][2], acc[mt][nt][3]);
                }
            }
        }
        __syncthreads();

        // LSTM cell: one per thread
        {
            float gi = gs0[cb * 32 + chl]      + gs0[(cb + 64) * 32 + chl]
                     + gs1[cb * 32 + chl]      + gs1[(cb + 64) * 32 + chl]      + pr0;
            float gf = gs0[cb * 32 + 8 + chl]  + gs0[(cb + 64) * 32 + 8 + chl]
                     + gs1[cb * 32 + 8 + chl]  + gs1[(cb + 64) * 32 + 8 + chl]  + pr1;
            float gg = gs0[cb * 32 + 16 + chl] + gs0[(cb + 64) * 32 + 16 + chl]
                     + gs1[cb * 32 + 16 + chl] + gs1[(cb + 64) * 32 + 16 + chl] + pr2;
            float go = gs0[cb * 32 + 24 + chl] + gs0[(cb + 64) * 32 + 24 + chl]
                     + gs1[cb * 32 + 24 + chl] + gs1[(cb + 64) * 32 + 24 + chl] + pr3;
            float si = sigm(gi), sf = sigm(gf), so = sigm(go);
            float tg = tanh_f(gg);
            float cn = sf * creg + si * tg;
            creg = cn;
            float hn = so * tanh_f(cn);

            long long srow = (long long)cb * T + t;
            __nv_bfloat16 hi = __float2bfloat16(hn);
            __nv_bfloat16 lo = __float2bfloat16(hn - __bfloat162float(hi));
            hout[cb * 1024 + chg] = hi;
            hout[(cb + 64) * 1024 + chg] = lo;
            if (spk) {
                spk[srow * 1024 + chg] = hi;
                spk[splane + srow * 1024 + chg] = lo;
            }
        }

        grid_bar(barid, t, NBLK);
    }

    cstate[cb * 1024 + chg] = creg;
}

// ----------------------- fused softmax + ctx + attn copy + row0 zero -----------------------
// grid (4, 64): block (q, b) handles t in [q*16, min(q*16+16, 63)); padded row -> zeros
__global__ void __launch_bounds__(256) ctx_fused(const float* __restrict__ scores,
                                                 const float* __restrict__ emb,
                                                 float* __restrict__ out) {
    int q = blockIdx.x, b = blockIdx.y;
    int t0 = q * 16;
    int nt = (t0 + 16 <= 63) ? 16 : (63 - t0);
    __shared__ float a[16][128];
    int tid = threadIdx.x;
    // load full 16 rows; pad out-of-range rows with 0 (softmax of zeros is harmless)
    for (int i = tid; i < 16 * 128; i += 256) {
        int tt = i >> 7, ss = i & 127;
        a[tt][ss] = (tt < nt) ? scores[((long long)b * 63 + t0 + tt) * 128 + ss] : 0.f;
    }
    __syncthreads();

    // softmax per row: 16 threads per row, 8 cols each; FULL participation (no guard)
    {
        int rr = tid >> 4, sub = tid & 15;
        float m = -1e30f;
#pragma unroll
        for (int j = 0; j < 8; j++) m = fmaxf(m, a[rr][sub * 8 + j]);
#pragma unroll
        for (int o = 8; o; o >>= 1) m = fmaxf(m, __shfl_xor_sync(0xffffffffu, m, o));
        float sum = 0.f;
        float ev[8];
#pragma unroll
        for (int j = 0; j < 8; j++) { ev[j] = __expf(a[rr][sub * 8 + j] - m); sum += ev[j]; }
#pragma unroll
        for (int o = 8; o; o >>= 1) sum += __shfl_xor_sync(0xffffffffu, sum, o);
        float inv = __fdividef(1.f, sum);
#pragma unroll
        for (int j = 0; j < 8; j++) a[rr][sub * 8 + j] = ev[j] * inv;
    }
    __syncthreads();

    // attn_weights output: row t=62 (block q=3, tt = 62-48 = 14)
    if (q == 3 && tid < 128)
        out[64LL * 64 * 512 + b * 128 + tid] = a[14][tid];
    // outputs[:,0,:] = 0 (block q=0)
    if (q == 0) {
        out[((long long)b * 64) * 512 + tid] = 0.f;
        out[((long long)b * 64) * 512 + tid + 256] = 0.f;
    }

    const float* e = emb + (long long)b * 128 * 512;
    int n0 = tid, n1 = tid + 256;
    float acc0[16], acc1[16];
#pragma unroll
    for (int i = 0; i < 16; i++) { acc0[i] = 0.f; acc1[i] = 0.f; }
    for (int s = 0; s < 128; s++) {
        float e0 = e[(long long)s * 512 + n0];
        float e1 = e[(long long)s * 512 + n1];
#pragma unroll
        for (int i = 0; i < 16; i++) {
            float av = a[i][s];
            acc0[i] += av * e0;
            acc1[i] += av * e1;
        }
    }
    for (int i = 0; i < nt; i++) {
        float* o = out + ((long long)b * 64 + (t0 + i + 1)) * 512;
        o[n0] = acc0[i];
        o[n1] = acc1[i];
    }
}

// ----------------------- host -----------------------
static float* addr_of(const void* symbol) {
    void* p = nullptr;
    cudaGetSymbolAddress(&p, symbol);
    return (float*)p;
}

extern "C" void kernel_launch(void* const* d_in, const int* in_sizes, int n_in,
                              void* d_out, int out_size) {
    const int*   src  = (const int*)d_in[0];
    const int*   trg  = (const int*)d_in[1];
    const float* srct = (const float*)d_in[2];
    const float* trgt = (const float*)d_in[3];
    const float* fcW  = (const float*)d_in[4];
    const float* fcb  = (const float*)d_in[5];
    const float* eW0  = (const float*)d_in[6];
    const float* eU0  = (const float*)d_in[7];
    const float* eb0  = (const float*)d_in[8];
    const float* ebb0 = (const float*)d_in[9];
    const float* eW1  = (const float*)d_in[10];
    const float* eU1  = (const float*)d_in[11];
    const float* eb1  = (const float*)d_in[12];
    const float* ebb1 = (const float*)d_in[13];
    const float* dW0  = (const float*)d_in[14];
    const float* dU0  = (const float*)d_in[15];
    const float* db0  = (const float*)d_in[16];
    const float* dbb0 = (const float*)d_in[17];
    const float* dW1  = (const float*)d_in[18];
    const float* dU1  = (const float*)d_in[19];
    const float* db1  = (const float*)d_in[20];
    const float* dbb1 = (const float*)d_in[21];
    float* out = (float*)d_out;

    float* srcemb = addr_of(g_srcemb);
    float* pre    = addr_of(g_pre);
    float* preds  = addr_of(g_preds);
    float* scores = addr_of(g_scores);
    float* cst    = addr_of(g_cstate);

    __nv_bfloat16* wpk    = (__nv_bfloat16*)addr_of(g_wpk);
    __nv_bfloat16* wihpk  = (__nv_bfloat16*)addr_of(g_wihpk);
    __nv_bfloat16* fcpk   = (__nv_bfloat16*)addr_of(g_fcpk);
    __nv_bfloat16* srcpk  = (__nv_bfloat16*)addr_of(g_srcpk);
    __nv_bfloat16* decpk  = (__nv_bfloat16*)addr_of(g_decpk);
    __nv_bfloat16* seqApk = (__nv_bfloat16*)addr_of(g_seqApk);
    __nv_bfloat16* dseqApk= (__nv_bfloat16*)addr_of(g_dseqApk);
    __nv_bfloat16* dseqBpk= (__nv_bfloat16*)addr_of(g_dseqBpk);
    __nv_bfloat16* hpk    = (__nv_bfloat16*)addr_of(g_hpk);

    const long long WPK_L  = 128LL * 64 * 1024;
    const long long WIH_L  = 2LL * 4096 * 1024;
    const long long HPK_P  = 128LL * 1024;
    __nv_bfloat16* hA0 = hpk,             * hA1 = hpk + HPK_P;
    __nv_bfloat16* hB0 = hpk + 2 * HPK_P, * hB1 = hpk + 3 * HPK_P;

    float* c0 = cst;
    float* c1 = cst + 64 * 1024;

    cudaFuncSetAttribute(lstm_layer_mma, cudaFuncAttributeMaxDynamicSharedMemorySize, LSTM_SMEM);
    cudaFuncSetAttribute(gemm_bf16, cudaFuncAttributeMaxDynamicSharedMemorySize, 2 * GB_STG);

    zero_init<<<512, 256>>>();
    prep_w4<<<dim3(512, 4), 256>>>(eU0, eU1, dU0, dU1);
    prep_all<<<dim3(1024, 5), 256>>>(eW0, eW1, dW0, dW1, fcW);
    gather_all<<<12224, 128>>>(src, trg, srct, trgt, srcemb, srcpk, decpk);

    // ---- encoder layer 0 ----
    gemm_bf16<<<dim3(64, 64), 256, 2 * GB_STG>>>(srcpk, wihpk + 0 * WIH_L, eb0, ebb0,
                                                 pre, 8192, 4096, 512);
    lstm_layer_mma<<<128, 512, LSTM_SMEM>>>(pre, wpk + 0 * WPK_L, hA0, hA1, c0,
                                            seqApk, 8192LL * 1024, 128, 0);
    // ---- encoder layer 1 ----
    gemm_bf16<<<dim3(64, 64), 256, 2 * GB_STG>>>(seqApk, wihpk + 1 * WIH_L, eb1, ebb1,
                                                 pre, 8192, 4096, 1024);
    lstm_layer_mma<<<128, 512, LSTM_SMEM>>>(pre, wpk + 1 * WPK_L, hB0, hB1, c1,
                                            nullptr, 0, 128, 1);
    // ---- decoder layer 0 (chain A continues) ----
    gemm_bf16<<<dim3(64, 32), 256, 2 * GB_STG>>>(decpk, wihpk + 2 * WIH_L, db0, dbb0,
                                                 pre, 4032, 4096, 512);
    lstm_layer_mma<<<128, 512, LSTM_SMEM>>>(pre, wpk + 2 * WPK_L, hA0, hA1, c0,
                                            dseqApk, 4032LL * 1024, 63, 2);
    // ---- decoder layer 1 (chain B continues) ----
    gemm_bf16<<<dim3(64, 32), 256, 2 * GB_STG>>>(dseqApk, wihpk + 3 * WIH_L, db1, dbb1,
                                                 pre, 4032, 4096, 1024);
    lstm_layer_mma<<<128, 512, LSTM_SMEM>>>(pre, wpk + 3 * WPK_L, hB0, hB1, c1,
                                            dseqBpk, 4032LL * 1024, 63, 3);

    // ---- fc (bf16 HMMA) ----
    gemm_bf16<<<dim3(8, 32), 256, 2 * GB_STG>>>(dseqBpk, fcpk, fcb, nullptr,
                                                preds, 4032, 512, 1024);

    // ---- attention scores ----
    float alpha = 1.f / sqrtf(512.f);
    gemm_abt<<<dim3(2, 1, 64), 256>>>(preds, srcemb, nullptr, nullptr, scores,
                                      63, 128, 512, alpha,
                                      (long long)63 * 512, (long long)128 * 512, (long long)63 * 128);
    // ---- fused softmax + ctx + attn copy + row0 zero ----
    ctx_fused<<<dim3(4, 64), 256>>>(scores, srcemb, out);
}